// round 10
// baseline (speedup 1.0000x reference)
#include <cuda_runtime.h>

typedef unsigned long long ull;

#define X7    (7*1048576)      // x[7] offset (floats)
#define W7OFF (7*8*4096)       // weights[7] offset (floats)

// Scratch (device globals — no allocations allowed)
__device__ float g_uhl[8*16384*64];  // [j][b][e] 32MB
__device__ float g_n2[8*16384];      // [j][b]
__device__ float g_umpart[32*512];   // per-block partial sums of u over b
__device__ float g_uhm[4096];        // [i][j][e]
__device__ float g_B[64];
__device__ float g_t[512];           // [j][d]
__device__ float g_c[8];             // final-iteration c_j

__device__ __forceinline__ void fma2(ull &acc, ull a, ull b) {
    asm("fma.rn.f32x2 %0, %1, %2, %0;" : "+l"(acc) : "l"(a), "l"(b));
}
__device__ __forceinline__ ull pack2(float x) {
    unsigned u = __float_as_uint(x);
    ull r; asm("mov.b64 %0, {%1, %1};" : "=l"(r) : "r"(u)); return r;
}
__device__ __forceinline__ float2 unpack2(ull v) {
    unsigned lo, hi;
    asm("mov.b64 {%0, %1}, %2;" : "=r"(lo), "=r"(hi) : "l"(v));
    return make_float2(__uint_as_float(lo), __uint_as_float(hi));
}
__device__ __forceinline__ float squash_scal(float cj, float n2v) {
    float s2 = cj*cj*n2v;
    return cj*s2 / ((1.f+s2)*sqrtf(s2+1e-9f));
}
// x[7] memory row for u-row b:  u[b,7,d] = x[7, b&31, b>>5, d]
__device__ __forceinline__ int xrow(int b) {
    return (b & 31)*512 + (b >> 5);
}

// sum over rows of x[i] -> g_umpart[bx][i*64+d]. float4 loads, no atomics.
__global__ __launch_bounds__(256) void k_umean(const float* __restrict__ x) {
    __shared__ float4 red[16][16];
    int i = blockIdx.y, bx = blockIdx.x, t = threadIdx.x;
    int dq = (t & 15) * 4, g = t >> 4;          // 16 d-quads, 16 row-groups
    const float* xp = x + i*1048576 + (bx*512 + g*32)*64 + dq;
    float4 acc = make_float4(0.f,0.f,0.f,0.f);
    #pragma unroll 8
    for (int m = 0; m < 32; m++) {
        float4 v = *(const float4*)(xp + m*64);
        acc.x += v.x; acc.y += v.y; acc.z += v.z; acc.w += v.w;
    }
    red[g][t & 15] = acc;
    __syncthreads();
    if (t < 16) {
        float4 s = make_float4(0.f,0.f,0.f,0.f);
        #pragma unroll
        for (int gg = 0; gg < 16; gg++) {
            float4 v = red[gg][t];
            s.x += v.x; s.y += v.y; s.z += v.z; s.w += v.w;
        }
        *(float4*)&g_umpart[bx*512 + i*64 + t*4] = s;
    }
}

// uhl[j,b,e] = sum_d u[b,7,d]*W7[j,d,e]; n2[j,b] = sum_e uhl^2
// grid (256 p-blocks, 4 j-pairs); 64 rows/block, 2 j per block.
__global__ __launch_bounds__(128, 6) void k_gemm(const float* __restrict__ x,
                                                 const float* __restrict__ w) {
    __shared__ float xs[64*64];    // [d][row] 16KB
    __shared__ float ws[64*64];    // [d][col] 16KB
    int t = threadIdx.x;           // 128
    int p0 = blockIdx.x * 64;      // b-block base
    int j0 = blockIdx.y * 2;

    if (blockIdx.x == 0 && blockIdx.y == 0) {   // zero routing state per replay
        g_t[t] = 0.f; g_t[t+128] = 0.f; g_t[t+256] = 0.f; g_t[t+384] = 0.f;
        if (t < 64) g_B[t] = 0.f;
    }

    {   // load + transpose 64 u-rows (gather from permuted x layout)
        int rp_ = t & 31, q = t >> 5;      // q: d-chunk of 16
        int bA = p0 + 2*rp_;
        const float* pa = x + X7 + xrow(bA)*64 + q*16;
        const float* pb = x + X7 + xrow(bA+1)*64 + q*16;
        #pragma unroll
        for (int i = 0; i < 4; i++) {
            float4 a = *(const float4*)(pa + 4*i);
            float4 b = *(const float4*)(pb + 4*i);
            int d0 = q*16 + 4*i;
            xs[(d0+0)*64 + 2*rp_] = a.x; xs[(d0+0)*64 + 2*rp_+1] = b.x;
            xs[(d0+1)*64 + 2*rp_] = a.y; xs[(d0+1)*64 + 2*rp_+1] = b.y;
            xs[(d0+2)*64 + 2*rp_] = a.z; xs[(d0+2)*64 + 2*rp_+1] = b.z;
            xs[(d0+3)*64 + 2*rp_] = a.w; xs[(d0+3)*64 + 2*rp_+1] = b.w;
        }
    }

    int cg = t & 7, rq = t >> 3;
    int r0 = rq * 4;

    #pragma unroll
    for (int jj = 0; jj < 2; jj++) {
        int j = j0 + jj;
        __syncthreads();
        {   // fill W tile (natural layout)
            const float* W7p = w + W7OFF + j*4096;
            #pragma unroll
            for (int k = 0; k < 8; k++) {
                int idx = t + 128*k;
                *(float4*)(ws + idx*4) = *(const float4*)(W7p + idx*4);
            }
        }
        __syncthreads();

        // acc[r][m]: m=0,1 -> cols 4cg..4cg+3 ; m=2,3 -> cols 32+4cg..+3
        ull acc[4][4];
        #pragma unroll
        for (int r = 0; r < 4; r++)
            #pragma unroll
            for (int m = 0; m < 4; m++) acc[r][m] = 0ULL;

        #pragma unroll 8
        for (int d = 0; d < 64; d++) {
            ulonglong2 w0 = *(const ulonglong2*)&ws[d*64 + cg*4];
            ulonglong2 w1 = *(const ulonglong2*)&ws[d*64 + 32 + cg*4];
            ull xr[4];
            #pragma unroll
            for (int r = 0; r < 4; r++) xr[r] = pack2(xs[d*64 + r0 + r]);
            #pragma unroll
            for (int r = 0; r < 4; r++) {
                fma2(acc[r][0], xr[r], w0.x);
                fma2(acc[r][1], xr[r], w0.y);
                fma2(acc[r][2], xr[r], w1.x);
                fma2(acc[r][3], xr[r], w1.y);
            }
        }

        #pragma unroll
        for (int r = 0; r < 4; r++) {
            float2 v0 = unpack2(acc[r][0]), v1 = unpack2(acc[r][1]);
            float2 v2 = unpack2(acc[r][2]), v3 = unpack2(acc[r][3]);
            int row = p0 + r0 + r;
            float* base = g_uhl + j*1048576 + row*64;
            *(float4*)(base + 4*cg)      = make_float4(v0.x, v0.y, v1.x, v1.y);
            *(float4*)(base + 32 + 4*cg) = make_float4(v2.x, v2.y, v3.x, v3.y);

            float s = v0.x*v0.x + v0.y*v0.y + v1.x*v1.x + v1.y*v1.y
                    + v2.x*v2.x + v2.y*v2.y + v3.x*v3.x + v3.y*v3.y;
            #pragma unroll
            for (int off = 1; off < 8; off <<= 1)
                s += __shfl_xor_sync(~0u, s, off);
            if (cg == 0) g_n2[j*16384 + row] = s;
        }
    }
}

// one routing reduction: c=softmax(B)[7,:]; t[j,d] += scal(b,j)*u[b,7,d]
// grid 512 blocks x 32 rows; 8 loads batched in regs before FMA chain.
__global__ __launch_bounds__(256) void k_route1(const float* __restrict__ x) {
    __shared__ float c_s[8];
    __shared__ float scal_s[32*8];
    __shared__ float red[4][512];
    int t = threadIdx.x;
    if (t < 8) {
        float m = g_B[t];
        #pragma unroll
        for (int i = 1; i < 8; i++) m = fmaxf(m, g_B[i*8+t]);
        float sum = 0.f, e7 = 0.f;
        #pragma unroll
        for (int i = 0; i < 8; i++) {
            float e = expf(g_B[i*8+t] - m);
            sum += e; if (i == 7) e7 = e;
        }
        c_s[t] = e7/sum;
    }
    __syncthreads();
    int p0 = blockIdx.x * 32;
    {   // scal table: 256 entries, 1 per thread
        int r = t >> 3, j = t & 7;
        scal_s[t] = squash_scal(c_s[j], g_n2[j*16384 + p0 + r]);
    }
    __syncthreads();
    int d = t & 63, g = t >> 6;          // 4 groups x 8 rows
    const float* xb = x + X7 + d;
    float xv[8];
    #pragma unroll
    for (int m = 0; m < 8; m++)          // 8 independent loads in flight
        xv[m] = xb[xrow(p0 + g*8 + m)*64];
    float acc[8] = {0,0,0,0,0,0,0,0};
    #pragma unroll
    for (int m = 0; m < 8; m++) {
        int r = g*8 + m;
        #pragma unroll
        for (int j = 0; j < 8; j++) acc[j] += scal_s[r*8+j] * xv[m];
    }
    #pragma unroll
    for (int j = 0; j < 8; j++) red[g][j*64+d] = acc[j];
    __syncthreads();
    #pragma unroll
    for (int o = 0; o < 2; o++) {
        int idx = t + 256*o;
        atomicAdd(&g_t[idx], red[0][idx]+red[1][idx]+red[2][idx]+red[3][idx]);
    }
}

// vmean[j,e] = (1/16384)*sum_d W7[j,d,e]*t[j,d]; B += uhm.vmean; g_c=softmax(B)[7]
// First instance (UHM=true) also computes uhm from umpart.
template <bool UHM>
__global__ __launch_bounds__(512) void k_route2(const float* __restrict__ w) {
    __shared__ float ts[512], vm[512], um[512];
    int t = threadIdx.x;           // 512
    if (UHM) {
        float s = 0.f;
        #pragma unroll
        for (int bx = 0; bx < 32; bx++) s += g_umpart[bx*512 + t];
        um[t] = s * (1.f/16384.f);
    }
    ts[t] = g_t[t];
    __syncthreads();
    g_t[t] = 0.f;
    const float* W7p = w + W7OFF;
    if (UHM) {
        // uhm[i,j,e] = sum_d W[i,j,d,e]*um[i,d]; 4096 outputs, 8 per thread
        #pragma unroll
        for (int o = 0; o < 8; o++) {
            int idx = t + 512*o;
            int i = idx >> 9, e = idx & 63, ij = idx >> 6;
            const float* wp = w + ij*4096 + e;
            const float* up = um + i*64;
            float s = 0.f;
            #pragma unroll 8
            for (int d = 0; d < 64; d++) s += wp[d*64] * up[d];
            g_uhm[idx] = s;
        }
    }
    {
        int j = t >> 6, e = t & 63;
        const float* wp = W7p + j*4096 + e;
        const float* tp = ts + j*64;
        float s = 0.f;
        #pragma unroll 8
        for (int d = 0; d < 64; d++) s += wp[d*64] * tp[d];
        vm[t] = s * (1.f/16384.f);
    }
    __syncthreads();
    if (t < 64) {
        int j = t & 7;
        float s = 0.f;
        #pragma unroll 8
        for (int e = 0; e < 64; e++) s += g_uhm[t*64 + e] * vm[j*64 + e];
        g_B[t] += s;
    }
    __syncthreads();
    if (t < 8) {
        float m = g_B[t];
        #pragma unroll
        for (int i = 1; i < 8; i++) m = fmaxf(m, g_B[i*8+t]);
        float sum = 0.f, e7 = 0.f;
        #pragma unroll
        for (int i = 0; i < 8; i++) {
            float e = expf(g_B[i*8+t] - m);
            sum += e; if (i == 7) e7 = e;
        }
        g_c[t] = e7/sum;
    }
}

// out[j,b,e] = scal3(j,b) * uhl[j,b,e]  (pure stream; output position == b)
__global__ void k_out(float* __restrict__ out) {
    __shared__ float scal_s[128];
    int j = blockIdx.y, p0 = blockIdx.x * 128, t = threadIdx.x;
    if (t < 128) scal_s[t] = squash_scal(g_c[j], g_n2[j*16384 + p0 + t]);
    __syncthreads();
    const float4* src = (const float4*)(g_uhl + j*1048576 + p0*64);
    float4* dst = (float4*)(out + j*1048576 + p0*64);
    #pragma unroll
    for (int k = 0; k < 8; k++) {
        int idx = k*256 + t;       // 2048 float4
        float4 v = src[idx];
        float s = scal_s[idx >> 4];
        v.x *= s; v.y *= s; v.z *= s; v.w *= s;
        dst[idx] = v;
    }
}

extern "C" void kernel_launch(void* const* d_in, const int* in_sizes, int n_in,
                              void* d_out, int out_size) {
    const float* x = (const float*)d_in[0];
    const float* w = (const float*)d_in[1];
    float* out = (float*)d_out;
    k_gemm<<<dim3(256, 4), 128>>>(x, w);
    k_umean<<<dim3(32, 8), 256>>>(x);
    k_route1<<<512, 256>>>(x);
    k_route2<true><<<1, 512>>>(w);
    k_route1<<<512, 256>>>(x);
    k_route2<false><<<1, 512>>>(w);
    k_out<<<dim3(128, 8), 256>>>(out);
}

// round 11
// speedup vs baseline: 1.2735x; 1.2735x over previous
#include <cuda_runtime.h>

typedef unsigned long long ull;

#define X7    (7*1048576)      // x[7] offset (floats)
#define W7OFF (7*8*4096)       // weights[7] offset (floats)

// Scratch (device globals — no allocations allowed)
__device__ float g_uhl[8*16384*64];  // [j][b][e] 32MB
__device__ float g_n2[8*16384];      // [j][b]
__device__ float g_umpart[32*512];   // per-block partial sums of u over b
__device__ float g_uhm[4096];        // [i][j][e]
__device__ float g_B[64];
__device__ float g_t[512];           // [j][d]
__device__ float g_c[8];             // final-iteration c_j

__device__ __forceinline__ void fma2(ull &acc, ull a, ull b) {
    asm("fma.rn.f32x2 %0, %1, %2, %0;" : "+l"(acc) : "l"(a), "l"(b));
}
__device__ __forceinline__ ull pack2(float x) {
    unsigned u = __float_as_uint(x);
    ull r; asm("mov.b64 %0, {%1, %1};" : "=l"(r) : "r"(u)); return r;
}
__device__ __forceinline__ float2 unpack2(ull v) {
    unsigned lo, hi;
    asm("mov.b64 {%0, %1}, %2;" : "=r"(lo), "=r"(hi) : "l"(v));
    return make_float2(__uint_as_float(lo), __uint_as_float(hi));
}
__device__ __forceinline__ float squash_scal(float cj, float n2v) {
    float s2 = cj*cj*n2v;
    return cj*s2 / ((1.f+s2)*sqrtf(s2+1e-9f));
}
// x[7] memory row for u-row b:  u[b,7,d] = x[7, b&31, b>>5, d]
__device__ __forceinline__ int xrow(int b) {
    return (b & 31)*512 + (b >> 5);
}

// sum over rows of x[i] -> g_umpart[bx][i*64+d]. float4 loads, no atomics.
__global__ __launch_bounds__(256) void k_umean(const float* __restrict__ x) {
    __shared__ float4 red[16][16];
    int i = blockIdx.y, bx = blockIdx.x, t = threadIdx.x;
    int dq = (t & 15) * 4, g = t >> 4;          // 16 d-quads, 16 row-groups
    const float* xp = x + i*1048576 + (bx*512 + g*32)*64 + dq;
    float4 acc = make_float4(0.f,0.f,0.f,0.f);
    #pragma unroll 8
    for (int m = 0; m < 32; m++) {
        float4 v = *(const float4*)(xp + m*64);
        acc.x += v.x; acc.y += v.y; acc.z += v.z; acc.w += v.w;
    }
    red[g][t & 15] = acc;
    __syncthreads();
    if (t < 16) {
        float4 s = make_float4(0.f,0.f,0.f,0.f);
        #pragma unroll
        for (int gg = 0; gg < 16; gg++) {
            float4 v = red[gg][t];
            s.x += v.x; s.y += v.y; s.z += v.z; s.w += v.w;
        }
        *(float4*)&g_umpart[bx*512 + i*64 + t*4] = s;
    }
}

// uhm[i,j,e] = sum_d W[i,j,d,e] * umean[i,d]   (16 blocks x 4 ij each)
__global__ __launch_bounds__(256) void k_uhm(const float* __restrict__ w) {
    __shared__ float um[512];
    int t = threadIdx.x;           // 256
    #pragma unroll
    for (int o = 0; o < 2; o++) {
        int idx = t + 256*o;
        float s = 0.f;
        #pragma unroll
        for (int bx = 0; bx < 32; bx++) s += g_umpart[bx*512 + idx];
        um[idx] = s * (1.f/16384.f);
    }
    __syncthreads();
    int ij = blockIdx.x*4 + (t >> 6), e = t & 63;
    int i = ij >> 3;
    const float* wp = w + ij*4096 + e;
    const float* up = um + i*64;
    float s = 0.f;
    #pragma unroll 8
    for (int d = 0; d < 64; d++) s += wp[d*64] * up[d];
    g_uhm[ij*64 + e] = s;
}

// uhl[j,b,e] = sum_d u[b,7,d]*W7[j,d,e]; n2[j,b] = sum_e uhl^2
// grid (256 p-blocks, 4 j-pairs); 64 rows/block, 2 j per block.
__global__ __launch_bounds__(128, 6) void k_gemm(const float* __restrict__ x,
                                                 const float* __restrict__ w) {
    __shared__ float xs[64*64];    // [d][row] 16KB
    __shared__ float ws[64*64];    // [d][col] 16KB
    int t = threadIdx.x;           // 128
    int p0 = blockIdx.x * 64;      // b-block base
    int j0 = blockIdx.y * 2;

    if (blockIdx.x == 0 && blockIdx.y == 0) {   // zero routing state per replay
        g_t[t] = 0.f; g_t[t+128] = 0.f; g_t[t+256] = 0.f; g_t[t+384] = 0.f;
        if (t < 64) g_B[t] = 0.f;
    }

    {   // load + transpose 64 u-rows (gather from permuted x layout)
        int rp_ = t & 31, q = t >> 5;      // q: d-chunk of 16
        int bA = p0 + 2*rp_;
        const float* pa = x + X7 + xrow(bA)*64 + q*16;
        const float* pb = x + X7 + xrow(bA+1)*64 + q*16;
        #pragma unroll
        for (int i = 0; i < 4; i++) {
            float4 a = *(const float4*)(pa + 4*i);
            float4 b = *(const float4*)(pb + 4*i);
            int d0 = q*16 + 4*i;
            xs[(d0+0)*64 + 2*rp_] = a.x; xs[(d0+0)*64 + 2*rp_+1] = b.x;
            xs[(d0+1)*64 + 2*rp_] = a.y; xs[(d0+1)*64 + 2*rp_+1] = b.y;
            xs[(d0+2)*64 + 2*rp_] = a.z; xs[(d0+2)*64 + 2*rp_+1] = b.z;
            xs[(d0+3)*64 + 2*rp_] = a.w; xs[(d0+3)*64 + 2*rp_+1] = b.w;
        }
    }

    int cg = t & 7, rq = t >> 3;
    int r0 = rq * 4;

    #pragma unroll
    for (int jj = 0; jj < 2; jj++) {
        int j = j0 + jj;
        __syncthreads();
        {   // fill W tile (natural layout)
            const float* W7p = w + W7OFF + j*4096;
            #pragma unroll
            for (int k = 0; k < 8; k++) {
                int idx = t + 128*k;
                *(float4*)(ws + idx*4) = *(const float4*)(W7p + idx*4);
            }
        }
        __syncthreads();

        // acc[r][m]: m=0,1 -> cols 4cg..4cg+3 ; m=2,3 -> cols 32+4cg..+3
        ull acc[4][4];
        #pragma unroll
        for (int r = 0; r < 4; r++)
            #pragma unroll
            for (int m = 0; m < 4; m++) acc[r][m] = 0ULL;

        #pragma unroll 8
        for (int d = 0; d < 64; d++) {
            ulonglong2 w0 = *(const ulonglong2*)&ws[d*64 + cg*4];
            ulonglong2 w1 = *(const ulonglong2*)&ws[d*64 + 32 + cg*4];
            ull xr[4];
            #pragma unroll
            for (int r = 0; r < 4; r++) xr[r] = pack2(xs[d*64 + r0 + r]);
            #pragma unroll
            for (int r = 0; r < 4; r++) {
                fma2(acc[r][0], xr[r], w0.x);
                fma2(acc[r][1], xr[r], w0.y);
                fma2(acc[r][2], xr[r], w1.x);
                fma2(acc[r][3], xr[r], w1.y);
            }
        }

        #pragma unroll
        for (int r = 0; r < 4; r++) {
            float2 v0 = unpack2(acc[r][0]), v1 = unpack2(acc[r][1]);
            float2 v2 = unpack2(acc[r][2]), v3 = unpack2(acc[r][3]);
            int row = p0 + r0 + r;
            float* base = g_uhl + j*1048576 + row*64;
            *(float4*)(base + 4*cg)      = make_float4(v0.x, v0.y, v1.x, v1.y);
            *(float4*)(base + 32 + 4*cg) = make_float4(v2.x, v2.y, v3.x, v3.y);

            float s = v0.x*v0.x + v0.y*v0.y + v1.x*v1.x + v1.y*v1.y
                    + v2.x*v2.x + v2.y*v2.y + v3.x*v3.x + v3.y*v3.y;
            #pragma unroll
            for (int off = 1; off < 8; off <<= 1)
                s += __shfl_xor_sync(~0u, s, off);
            if (cg == 0) g_n2[j*16384 + row] = s;
        }
    }
}

// one routing reduction: c=softmax(B)[7,:]; t[j,d] += scal(b,j)*u[b,7,d]
// grid 512 blocks x 32 rows; 8 loads batched in regs before FMA chain.
__global__ __launch_bounds__(256) void k_route1(const float* __restrict__ x) {
    __shared__ float c_s[8];
    __shared__ float scal_s[32*8];
    __shared__ float red[4][512];
    int t = threadIdx.x;
    if (t < 8) {
        float m = g_B[t];
        #pragma unroll
        for (int i = 1; i < 8; i++) m = fmaxf(m, g_B[i*8+t]);
        float sum = 0.f, e7 = 0.f;
        #pragma unroll
        for (int i = 0; i < 8; i++) {
            float e = expf(g_B[i*8+t] - m);
            sum += e; if (i == 7) e7 = e;
        }
        c_s[t] = e7/sum;
    }
    __syncthreads();
    int p0 = blockIdx.x * 32;
    {   // scal table: 256 entries, 1 per thread
        int r = t >> 3, j = t & 7;
        scal_s[t] = squash_scal(c_s[j], g_n2[j*16384 + p0 + r]);
    }
    __syncthreads();
    int d = t & 63, g = t >> 6;          // 4 groups x 8 rows
    const float* xb = x + X7 + d;
    float xv[8];
    #pragma unroll
    for (int m = 0; m < 8; m++)          // 8 independent loads in flight
        xv[m] = xb[xrow(p0 + g*8 + m)*64];
    float acc[8] = {0,0,0,0,0,0,0,0};
    #pragma unroll
    for (int m = 0; m < 8; m++) {
        int r = g*8 + m;
        #pragma unroll
        for (int j = 0; j < 8; j++) acc[j] += scal_s[r*8+j] * xv[m];
    }
    #pragma unroll
    for (int j = 0; j < 8; j++) red[g][j*64+d] = acc[j];
    __syncthreads();
    #pragma unroll
    for (int o = 0; o < 2; o++) {
        int idx = t + 256*o;
        atomicAdd(&g_t[idx], red[0][idx]+red[1][idx]+red[2][idx]+red[3][idx]);
    }
}

// vmean[j,e] = (1/16384)*sum_d W7[j,d,e]*t[j,d]; B += uhm.vmean; g_c=softmax(B)[7]
__global__ __launch_bounds__(512) void k_route2(const float* __restrict__ w) {
    __shared__ float ts[512], vm[512];
    int t = threadIdx.x;           // 512
    ts[t] = g_t[t];
    __syncthreads();
    g_t[t] = 0.f;
    const float* W7p = w + W7OFF;
    {
        int j = t >> 6, e = t & 63;
        const float* wp = W7p + j*4096 + e;
        const float* tp = ts + j*64;
        float s = 0.f;
        #pragma unroll 8
        for (int d = 0; d < 64; d++) s += wp[d*64] * tp[d];
        vm[t] = s * (1.f/16384.f);
    }
    __syncthreads();
    if (t < 64) {
        int j = t & 7;
        float s = 0.f;
        #pragma unroll 8
        for (int e = 0; e < 64; e++) s += g_uhm[t*64 + e] * vm[j*64 + e];
        g_B[t] += s;
    }
    __syncthreads();
    if (t < 8) {
        float m = g_B[t];
        #pragma unroll
        for (int i = 1; i < 8; i++) m = fmaxf(m, g_B[i*8+t]);
        float sum = 0.f, e7 = 0.f;
        #pragma unroll
        for (int i = 0; i < 8; i++) {
            float e = expf(g_B[i*8+t] - m);
            sum += e; if (i == 7) e7 = e;
        }
        g_c[t] = e7/sum;
    }
}

// out[j,b,e] = scal3(j,b) * uhl[j,b,e]  (pure stream; output position == b)
__global__ void k_out(float* __restrict__ out) {
    __shared__ float scal_s[128];
    int j = blockIdx.y, p0 = blockIdx.x * 128, t = threadIdx.x;
    if (t < 128) scal_s[t] = squash_scal(g_c[j], g_n2[j*16384 + p0 + t]);
    __syncthreads();
    const float4* src = (const float4*)(g_uhl + j*1048576 + p0*64);
    float4* dst = (float4*)(out + j*1048576 + p0*64);
    #pragma unroll
    for (int k = 0; k < 8; k++) {
        int idx = k*256 + t;       // 2048 float4
        float4 v = src[idx];
        float s = scal_s[idx >> 4];
        v.x *= s; v.y *= s; v.z *= s; v.w *= s;
        dst[idx] = v;
    }
}

extern "C" void kernel_launch(void* const* d_in, const int* in_sizes, int n_in,
                              void* d_out, int out_size) {
    const float* x = (const float*)d_in[0];
    const float* w = (const float*)d_in[1];
    float* out = (float*)d_out;
    k_gemm<<<dim3(256, 4), 128>>>(x, w);
    k_umean<<<dim3(32, 8), 256>>>(x);
    k_uhm<<<16, 256>>>(w);
    k_route1<<<512, 256>>>(x);
    k_route2<<<1, 512>>>(w);
    k_route1<<<512, 256>>>(x);
    k_route2<<<1, 512>>>(w);
    k_out<<<dim3(128, 8), 256>>>(out);
}

// round 12
// speedup vs baseline: 1.3101x; 1.0288x over previous
#include <cuda_runtime.h>

typedef unsigned long long ull;

#define X7    (7*1048576)      // x[7] offset (floats)
#define W7OFF (7*8*4096)       // weights[7] offset (floats)

// Scratch (device globals — no allocations allowed)
__device__ float g_uhl[8*16384*64];  // [j][b][e] 32MB
__device__ float g_n2[8*16384];      // [j][b]
__device__ float g_umpart[32*512];   // per-block partial sums of u over b
__device__ float g_uhm[4096];        // [i][j][e]
__device__ float g_B[64];
__device__ float g_t[512];           // [j][d]  (zero at replay start; route2 re-zeroes)
__device__ float g_c[8];             // final-iteration c_j

__device__ __forceinline__ void fma2(ull &acc, ull a, ull b) {
    asm("fma.rn.f32x2 %0, %1, %2, %0;" : "+l"(acc) : "l"(a), "l"(b));
}
__device__ __forceinline__ ull pack2(float x) {
    unsigned u = __float_as_uint(x);
    ull r; asm("mov.b64 %0, {%1, %1};" : "=l"(r) : "r"(u)); return r;
}
__device__ __forceinline__ float2 unpack2(ull v) {
    unsigned lo, hi;
    asm("mov.b64 {%0, %1}, %2;" : "=r"(lo), "=r"(hi) : "l"(v));
    return make_float2(__uint_as_float(lo), __uint_as_float(hi));
}
__device__ __forceinline__ float squash_scal(float cj, float n2v) {
    float s2 = cj*cj*n2v;
    return cj*s2 / ((1.f+s2)*sqrtf(s2+1e-9f));
}
// x[7] memory row for u-row b:  u[b,7,d] = x[7, b&31, b>>5, d]
__device__ __forceinline__ int xrow(int b) {
    return (b & 31)*512 + (b >> 5);
}

// sum over rows of x[i] -> g_umpart[bx][i*64+d]. float4 loads, no atomics.
__global__ __launch_bounds__(256) void k_umean(const float* __restrict__ x) {
    __shared__ float4 red[16][16];
    int i = blockIdx.y, bx = blockIdx.x, t = threadIdx.x;
    int dq = (t & 15) * 4, g = t >> 4;          // 16 d-quads, 16 row-groups
    const float* xp = x + i*1048576 + (bx*512 + g*32)*64 + dq;
    float4 acc = make_float4(0.f,0.f,0.f,0.f);
    #pragma unroll 8
    for (int m = 0; m < 32; m++) {
        float4 v = *(const float4*)(xp + m*64);
        acc.x += v.x; acc.y += v.y; acc.z += v.z; acc.w += v.w;
    }
    red[g][t & 15] = acc;
    __syncthreads();
    if (t < 16) {
        float4 s = make_float4(0.f,0.f,0.f,0.f);
        #pragma unroll
        for (int gg = 0; gg < 16; gg++) {
            float4 v = red[gg][t];
            s.x += v.x; s.y += v.y; s.z += v.z; s.w += v.w;
        }
        *(float4*)&g_umpart[bx*512 + i*64 + t*4] = s;
    }
}

// uhm[i,j,e] = sum_d W[i,j,d,e] * umean[i,d]   (16 blocks x 4 ij each)
__global__ __launch_bounds__(256) void k_uhm(const float* __restrict__ w) {
    __shared__ float um[512];
    int t = threadIdx.x;           // 256
    #pragma unroll
    for (int o = 0; o < 2; o++) {
        int idx = t + 256*o;
        float s = 0.f;
        #pragma unroll
        for (int bx = 0; bx < 32; bx++) s += g_umpart[bx*512 + idx];
        um[idx] = s * (1.f/16384.f);
    }
    __syncthreads();
    int ij = blockIdx.x*4 + (t >> 6), e = t & 63;
    int i = ij >> 3;
    const float* wp = w + ij*4096 + e;
    const float* up = um + i*64;
    float s = 0.f;
    #pragma unroll 8
    for (int d = 0; d < 64; d++) s += wp[d*64] * up[d];
    g_uhm[ij*64 + e] = s;
}

// uhl[j,b,e] = sum_d u[b,7,d]*W7[j,d,e]; n2[j,b] = sum_e uhl^2.
// ALSO fuses routing iteration 1 (c = 1/8 exactly since B=0):
//   g_t[j,d] += sum_b squash_scal(1/8, n2[b,j]) * u[b,7,d]
// grid (256 p-blocks, 4 j-pairs); 64 rows/block, 2 j per block.
__global__ __launch_bounds__(128, 6) void k_gemm(const float* __restrict__ x,
                                                 const float* __restrict__ w) {
    __shared__ float xs[64*65];      // [d][row], stride 65 (conflict-free column reads)
    __shared__ float ws[64*64];      // [d][col] 16KB
    __shared__ float scal_sm[2][64]; // squash_scal(1/8, n2) per (jj, row)
    int t = threadIdx.x;             // 128
    int p0 = blockIdx.x * 64;        // b-block base
    int j0 = blockIdx.y * 2;

    {   // load + transpose 64 u-rows (gather from permuted x layout)
        int rp_ = t & 31, q = t >> 5;      // q: d-chunk of 16
        int bA = p0 + 2*rp_;
        const float* pa = x + X7 + xrow(bA)*64 + q*16;
        const float* pb = x + X7 + xrow(bA+1)*64 + q*16;
        #pragma unroll
        for (int i = 0; i < 4; i++) {
            float4 a = *(const float4*)(pa + 4*i);
            float4 b = *(const float4*)(pb + 4*i);
            int d0 = q*16 + 4*i;
            xs[(d0+0)*65 + 2*rp_] = a.x; xs[(d0+0)*65 + 2*rp_+1] = b.x;
            xs[(d0+1)*65 + 2*rp_] = a.y; xs[(d0+1)*65 + 2*rp_+1] = b.y;
            xs[(d0+2)*65 + 2*rp_] = a.z; xs[(d0+2)*65 + 2*rp_+1] = b.z;
            xs[(d0+3)*65 + 2*rp_] = a.w; xs[(d0+3)*65 + 2*rp_+1] = b.w;
        }
    }

    int cg = t & 7, rq = t >> 3;
    int r0 = rq * 4;

    #pragma unroll
    for (int jj = 0; jj < 2; jj++) {
        int j = j0 + jj;
        __syncthreads();
        {   // fill W tile (natural layout)
            const float* W7p = w + W7OFF + j*4096;
            #pragma unroll
            for (int k = 0; k < 8; k++) {
                int idx = t + 128*k;
                *(float4*)(ws + idx*4) = *(const float4*)(W7p + idx*4);
            }
        }
        __syncthreads();

        // acc[r][m]: m=0,1 -> cols 4cg..4cg+3 ; m=2,3 -> cols 32+4cg..+3
        ull acc[4][4];
        #pragma unroll
        for (int r = 0; r < 4; r++)
            #pragma unroll
            for (int m = 0; m < 4; m++) acc[r][m] = 0ULL;

        #pragma unroll 8
        for (int d = 0; d < 64; d++) {
            ulonglong2 w0 = *(const ulonglong2*)&ws[d*64 + cg*4];
            ulonglong2 w1 = *(const ulonglong2*)&ws[d*64 + 32 + cg*4];
            ull xr[4];
            #pragma unroll
            for (int r = 0; r < 4; r++) xr[r] = pack2(xs[d*65 + r0 + r]);
            #pragma unroll
            for (int r = 0; r < 4; r++) {
                fma2(acc[r][0], xr[r], w0.x);
                fma2(acc[r][1], xr[r], w0.y);
                fma2(acc[r][2], xr[r], w1.x);
                fma2(acc[r][3], xr[r], w1.y);
            }
        }

        #pragma unroll
        for (int r = 0; r < 4; r++) {
            float2 v0 = unpack2(acc[r][0]), v1 = unpack2(acc[r][1]);
            float2 v2 = unpack2(acc[r][2]), v3 = unpack2(acc[r][3]);
            int row = p0 + r0 + r;
            float* base = g_uhl + j*1048576 + row*64;
            *(float4*)(base + 4*cg)      = make_float4(v0.x, v0.y, v1.x, v1.y);
            *(float4*)(base + 32 + 4*cg) = make_float4(v2.x, v2.y, v3.x, v3.y);

            float s = v0.x*v0.x + v0.y*v0.y + v1.x*v1.x + v1.y*v1.y
                    + v2.x*v2.x + v2.y*v2.y + v3.x*v3.x + v3.y*v3.y;
            #pragma unroll
            for (int off = 1; off < 8; off <<= 1)
                s += __shfl_xor_sync(~0u, s, off);
            if (cg == 0) {
                g_n2[j*16384 + row] = s;
                scal_sm[jj][r0 + r] = squash_scal(0.125f, s);
            }
        }
    }

    // Fused routing iteration 1: t1[jj][d] = sum_r scal_sm[jj][r] * x[r][d]
    __syncthreads();
    {
        int d = t & 63, jj2 = t >> 6;
        float acc = 0.f;
        #pragma unroll 16
        for (int r = 0; r < 64; r++)
            acc += scal_sm[jj2][r] * xs[d*65 + r];
        atomicAdd(&g_t[(j0 + jj2)*64 + d], acc);
    }
}

// one routing reduction: c=softmax(B)[7,:]; t[j,d] += scal(b,j)*u[b,7,d]
// grid 512 blocks x 32 rows; 8 loads batched in regs before FMA chain.
__global__ __launch_bounds__(256) void k_route1(const float* __restrict__ x) {
    __shared__ float c_s[8];
    __shared__ float scal_s[32*8];
    __shared__ float red[4][512];
    int t = threadIdx.x;
    if (t < 8) {
        float m = g_B[t];
        #pragma unroll
        for (int i = 1; i < 8; i++) m = fmaxf(m, g_B[i*8+t]);
        float sum = 0.f, e7 = 0.f;
        #pragma unroll
        for (int i = 0; i < 8; i++) {
            float e = expf(g_B[i*8+t] - m);
            sum += e; if (i == 7) e7 = e;
        }
        c_s[t] = e7/sum;
    }
    __syncthreads();
    int p0 = blockIdx.x * 32;
    {   // scal table: 256 entries, 1 per thread
        int r = t >> 3, j = t & 7;
        scal_s[t] = squash_scal(c_s[j], g_n2[j*16384 + p0 + r]);
    }
    __syncthreads();
    int d = t & 63, g = t >> 6;          // 4 groups x 8 rows
    const float* xb = x + X7 + d;
    float xv[8];
    #pragma unroll
    for (int m = 0; m < 8; m++)          // 8 independent loads in flight
        xv[m] = xb[xrow(p0 + g*8 + m)*64];
    float acc[8] = {0,0,0,0,0,0,0,0};
    #pragma unroll
    for (int m = 0; m < 8; m++) {
        int r = g*8 + m;
        #pragma unroll
        for (int j = 0; j < 8; j++) acc[j] += scal_s[r*8+j] * xv[m];
    }
    #pragma unroll
    for (int j = 0; j < 8; j++) red[g][j*64+d] = acc[j];
    __syncthreads();
    #pragma unroll
    for (int o = 0; o < 2; o++) {
        int idx = t + 256*o;
        atomicAdd(&g_t[idx], red[0][idx]+red[1][idx]+red[2][idx]+red[3][idx]);
    }
}

// vmean[j,e] = (1/16384)*sum_d W7[j,d,e]*t[j,d]; B (=|+=) uhm.vmean; g_c=softmax(B)[7]
template <bool FIRST>
__global__ __launch_bounds__(512) void k_route2(const float* __restrict__ w) {
    __shared__ float ts[512], vm[512];
    int t = threadIdx.x;           // 512
    ts[t] = g_t[t];
    __syncthreads();
    g_t[t] = 0.f;                  // re-arm for next reduction / next replay
    const float* W7p = w + W7OFF;
    {
        int j = t >> 6, e = t & 63;
        const float* wp = W7p + j*4096 + e;
        const float* tp = ts + j*64;
        float s = 0.f;
        #pragma unroll 8
        for (int d = 0; d < 64; d++) s += wp[d*64] * tp[d];
        vm[t] = s * (1.f/16384.f);
    }
    __syncthreads();
    if (t < 64) {
        int j = t & 7;
        float s = 0.f;
        #pragma unroll 8
        for (int e = 0; e < 64; e++) s += g_uhm[t*64 + e] * vm[j*64 + e];
        if (FIRST) g_B[t] = s;     // B was 0 before iteration 1
        else       g_B[t] += s;
    }
    __syncthreads();
    if (t < 8) {
        float m = g_B[t];
        #pragma unroll
        for (int i = 1; i < 8; i++) m = fmaxf(m, g_B[i*8+t]);
        float sum = 0.f, e7 = 0.f;
        #pragma unroll
        for (int i = 0; i < 8; i++) {
            float e = expf(g_B[i*8+t] - m);
            sum += e; if (i == 7) e7 = e;
        }
        g_c[t] = e7/sum;
    }
}

// out[j,b,e] = scal3(j,b) * uhl[j,b,e]  (pure stream; output position == b)
__global__ void k_out(float* __restrict__ out) {
    __shared__ float scal_s[128];
    int j = blockIdx.y, p0 = blockIdx.x * 128, t = threadIdx.x;
    if (t < 128) scal_s[t] = squash_scal(g_c[j], g_n2[j*16384 + p0 + t]);
    __syncthreads();
    const float4* src = (const float4*)(g_uhl + j*1048576 + p0*64);
    float4* dst = (float4*)(out + j*1048576 + p0*64);
    #pragma unroll
    for (int k = 0; k < 8; k++) {
        int idx = k*256 + t;       // 2048 float4
        float4 v = src[idx];
        float s = scal_s[idx >> 4];
        v.x *= s; v.y *= s; v.z *= s; v.w *= s;
        dst[idx] = v;
    }
}

extern "C" void kernel_launch(void* const* d_in, const int* in_sizes, int n_in,
                              void* d_out, int out_size) {
    const float* x = (const float*)d_in[0];
    const float* w = (const float*)d_in[1];
    float* out = (float*)d_out;
    k_gemm<<<dim3(256, 4), 128>>>(x, w);       // uhl, n2, t1 (c=1/8)
    k_umean<<<dim3(32, 8), 256>>>(x);
    k_uhm<<<16, 256>>>(w);
    k_route2<true><<<1, 512>>>(w);             // B1, c2
    k_route1<<<512, 256>>>(x);                 // t2
    k_route2<false><<<1, 512>>>(w);            // B2, c3
    k_out<<<dim3(128, 8), 256>>>(out);
}

// round 13
// speedup vs baseline: 1.4105x; 1.0766x over previous
#include <cuda_runtime.h>

typedef unsigned long long ull;

#define X7    (7*1048576)      // x[7] offset (floats)
#define W7OFF (7*8*4096)       // weights[7] offset (floats)

// Scratch (device globals — no allocations allowed)
__device__ float g_uhl[8*16384*64];  // [j][b][e] 32MB
__device__ float g_n2[8*16384];      // [j][b]
__device__ float g_umpart[32*512];   // per-block partial sums of u over b
__device__ float g_M[4096];          // M[i,j,d] = sum_e uhm[i,j,e]*W7[j,d,e]
__device__ float g_B[64];
__device__ float g_t[512];           // [j][d]  (zero at replay start; route2 re-zeroes)
__device__ float g_c[8];             // final-iteration c_j

__device__ __forceinline__ void fma2(ull &acc, ull a, ull b) {
    asm("fma.rn.f32x2 %0, %1, %2, %0;" : "+l"(acc) : "l"(a), "l"(b));
}
__device__ __forceinline__ ull pack2(float x) {
    unsigned u = __float_as_uint(x);
    ull r; asm("mov.b64 %0, {%1, %1};" : "=l"(r) : "r"(u)); return r;
}
__device__ __forceinline__ float2 unpack2(ull v) {
    unsigned lo, hi;
    asm("mov.b64 {%0, %1}, %2;" : "=r"(lo), "=r"(hi) : "l"(v));
    return make_float2(__uint_as_float(lo), __uint_as_float(hi));
}
__device__ __forceinline__ float squash_scal(float cj, float n2v) {
    float s2 = cj*cj*n2v;
    return cj*s2 / ((1.f+s2)*sqrtf(s2+1e-9f));
}
// x[7] memory row for u-row b:  u[b,7,d] = x[7, b&31, b>>5, d]
__device__ __forceinline__ int xrow(int b) {
    return (b & 31)*512 + (b >> 5);
}

// sum over rows of x[i] -> g_umpart[bx][i*64+d]. float4 loads, no atomics.
__global__ __launch_bounds__(256) void k_umean(const float* __restrict__ x) {
    __shared__ float4 red[16][16];
    int i = blockIdx.y, bx = blockIdx.x, t = threadIdx.x;
    int dq = (t & 15) * 4, g = t >> 4;          // 16 d-quads, 16 row-groups
    const float* xp = x + i*1048576 + (bx*512 + g*32)*64 + dq;
    float4 acc = make_float4(0.f,0.f,0.f,0.f);
    #pragma unroll 8
    for (int m = 0; m < 32; m++) {
        float4 v = *(const float4*)(xp + m*64);
        acc.x += v.x; acc.y += v.y; acc.z += v.z; acc.w += v.w;
    }
    red[g][t & 15] = acc;
    __syncthreads();
    if (t < 16) {
        float4 s = make_float4(0.f,0.f,0.f,0.f);
        #pragma unroll
        for (int gg = 0; gg < 16; gg++) {
            float4 v = red[gg][t];
            s.x += v.x; s.y += v.y; s.z += v.z; s.w += v.w;
        }
        *(float4*)&g_umpart[bx*512 + i*64 + t*4] = s;
    }
}

// uhm[i,j,e] = sum_d W[i,j,d,e]*umean[i,d]  (kept in smem), then
// M[i,j,d]  = sum_e uhm[i,j,e]*W7[j,d,e]   (contiguous W7 reads).
// 16 blocks x 4 ij each.
__global__ __launch_bounds__(256) void k_uhm(const float* __restrict__ w) {
    __shared__ float um[512];
    __shared__ float uhm_s[4][64];
    int t = threadIdx.x;           // 256
    #pragma unroll
    for (int o = 0; o < 2; o++) {
        int idx = t + 256*o;
        float s = 0.f;
        #pragma unroll
        for (int bx = 0; bx < 32; bx++) s += g_umpart[bx*512 + idx];
        um[idx] = s * (1.f/16384.f);
    }
    __syncthreads();
    int q = t >> 6, e = t & 63;    // q: local ij 0..3
    int ij = blockIdx.x*4 + q;
    int i = ij >> 3, j = ij & 7;
    {
        const float* wp = w + ij*4096 + e;
        const float* up = um + i*64;
        float s = 0.f;
        #pragma unroll 8
        for (int d = 0; d < 64; d++) s += wp[d*64] * up[d];
        uhm_s[q][e] = s;
    }
    __syncthreads();
    {   // M[ij, d]: d = e slot; W7[j,d,*] contiguous
        int d = e;
        const float4* wj = (const float4*)(w + W7OFF + j*4096 + d*64);
        const float* uh = uhm_s[q];
        float s = 0.f;
        #pragma unroll
        for (int k = 0; k < 16; k++) {
            float4 v = wj[k];
            s += uh[4*k]*v.x + uh[4*k+1]*v.y + uh[4*k+2]*v.z + uh[4*k+3]*v.w;
        }
        g_M[ij*64 + d] = s;
    }
}

// uhl[j,b,e] = sum_d u[b,7,d]*W7[j,d,e]; n2[j,b] = sum_e uhl^2.
// ALSO fuses routing iteration 1 (c = 1/8 exactly since B=0):
//   g_t[j,d] += sum_b squash_scal(1/8, n2[b,j]) * u[b,7,d]
// grid (256 p-blocks, 4 j-pairs); 64 rows/block, 2 j per block.
__global__ __launch_bounds__(128, 6) void k_gemm(const float* __restrict__ x,
                                                 const float* __restrict__ w) {
    __shared__ float xs[64*65];      // [d][row], stride 65 (conflict-free column reads)
    __shared__ float ws[64*64];      // [d][col] 16KB
    __shared__ float scal_sm[2][64]; // squash_scal(1/8, n2) per (jj, row)
    int t = threadIdx.x;             // 128
    int p0 = blockIdx.x * 64;        // b-block base
    int j0 = blockIdx.y * 2;

    {   // load + transpose 64 u-rows (gather from permuted x layout)
        int rp_ = t & 31, q = t >> 5;      // q: d-chunk of 16
        int bA = p0 + 2*rp_;
        const float* pa = x + X7 + xrow(bA)*64 + q*16;
        const float* pb = x + X7 + xrow(bA+1)*64 + q*16;
        #pragma unroll
        for (int i = 0; i < 4; i++) {
            float4 a = *(const float4*)(pa + 4*i);
            float4 b = *(const float4*)(pb + 4*i);
            int d0 = q*16 + 4*i;
            xs[(d0+0)*65 + 2*rp_] = a.x; xs[(d0+0)*65 + 2*rp_+1] = b.x;
            xs[(d0+1)*65 + 2*rp_] = a.y; xs[(d0+1)*65 + 2*rp_+1] = b.y;
            xs[(d0+2)*65 + 2*rp_] = a.z; xs[(d0+2)*65 + 2*rp_+1] = b.z;
            xs[(d0+3)*65 + 2*rp_] = a.w; xs[(d0+3)*65 + 2*rp_+1] = b.w;
        }
    }

    int cg = t & 7, rq = t >> 3;
    int r0 = rq * 4;

    #pragma unroll
    for (int jj = 0; jj < 2; jj++) {
        int j = j0 + jj;
        __syncthreads();
        {   // fill W tile (natural layout)
            const float* W7p = w + W7OFF + j*4096;
            #pragma unroll
            for (int k = 0; k < 8; k++) {
                int idx = t + 128*k;
                *(float4*)(ws + idx*4) = *(const float4*)(W7p + idx*4);
            }
        }
        __syncthreads();

        // acc[r][m]: m=0,1 -> cols 4cg..4cg+3 ; m=2,3 -> cols 32+4cg..+3
        ull acc[4][4];
        #pragma unroll
        for (int r = 0; r < 4; r++)
            #pragma unroll
            for (int m = 0; m < 4; m++) acc[r][m] = 0ULL;

        #pragma unroll 8
        for (int d = 0; d < 64; d++) {
            ulonglong2 w0 = *(const ulonglong2*)&ws[d*64 + cg*4];
            ulonglong2 w1 = *(const ulonglong2*)&ws[d*64 + 32 + cg*4];
            ull xr[4];
            #pragma unroll
            for (int r = 0; r < 4; r++) xr[r] = pack2(xs[d*65 + r0 + r]);
            #pragma unroll
            for (int r = 0; r < 4; r++) {
                fma2(acc[r][0], xr[r], w0.x);
                fma2(acc[r][1], xr[r], w0.y);
                fma2(acc[r][2], xr[r], w1.x);
                fma2(acc[r][3], xr[r], w1.y);
            }
        }

        #pragma unroll
        for (int r = 0; r < 4; r++) {
            float2 v0 = unpack2(acc[r][0]), v1 = unpack2(acc[r][1]);
            float2 v2 = unpack2(acc[r][2]), v3 = unpack2(acc[r][3]);
            int row = p0 + r0 + r;
            float* base = g_uhl + j*1048576 + row*64;
            *(float4*)(base + 4*cg)      = make_float4(v0.x, v0.y, v1.x, v1.y);
            *(float4*)(base + 32 + 4*cg) = make_float4(v2.x, v2.y, v3.x, v3.y);

            float s = v0.x*v0.x + v0.y*v0.y + v1.x*v1.x + v1.y*v1.y
                    + v2.x*v2.x + v2.y*v2.y + v3.x*v3.x + v3.y*v3.y;
            #pragma unroll
            for (int off = 1; off < 8; off <<= 1)
                s += __shfl_xor_sync(~0u, s, off);
            if (cg == 0) {
                g_n2[j*16384 + row] = s;
                scal_sm[jj][r0 + r] = squash_scal(0.125f, s);
            }
        }
    }

    // Fused routing iteration 1: t1[jj][d] = sum_r scal_sm[jj][r] * x[r][d]
    __syncthreads();
    {
        int d = t & 63, jj2 = t >> 6;
        float acc = 0.f;
        #pragma unroll 16
        for (int r = 0; r < 64; r++)
            acc += scal_sm[jj2][r] * xs[d*65 + r];
        atomicAdd(&g_t[(j0 + jj2)*64 + d], acc);
    }
}

// one routing reduction: c=softmax(B)[7,:]; t[j,d] += scal(b,j)*u[b,7,d]
// grid 512 blocks x 32 rows; 8 loads batched in regs before FMA chain.
__global__ __launch_bounds__(256) void k_route1(const float* __restrict__ x) {
    __shared__ float c_s[8];
    __shared__ float scal_s[32*8];
    __shared__ float red[4][512];
    int t = threadIdx.x;
    if (t < 8) {
        float m = g_B[t];
        #pragma unroll
        for (int i = 1; i < 8; i++) m = fmaxf(m, g_B[i*8+t]);
        float sum = 0.f, e7 = 0.f;
        #pragma unroll
        for (int i = 0; i < 8; i++) {
            float e = expf(g_B[i*8+t] - m);
            sum += e; if (i == 7) e7 = e;
        }
        c_s[t] = e7/sum;
    }
    __syncthreads();
    int p0 = blockIdx.x * 32;
    {   // scal table: 256 entries, 1 per thread
        int r = t >> 3, j = t & 7;
        scal_s[t] = squash_scal(c_s[j], g_n2[j*16384 + p0 + r]);
    }
    __syncthreads();
    int d = t & 63, g = t >> 6;          // 4 groups x 8 rows
    const float* xb = x + X7 + d;
    float xv[8];
    #pragma unroll
    for (int m = 0; m < 8; m++)          // 8 independent loads in flight
        xv[m] = xb[xrow(p0 + g*8 + m)*64];
    float acc[8] = {0,0,0,0,0,0,0,0};
    #pragma unroll
    for (int m = 0; m < 8; m++) {
        int r = g*8 + m;
        #pragma unroll
        for (int j = 0; j < 8; j++) acc[j] += scal_s[r*8+j] * xv[m];
    }
    #pragma unroll
    for (int j = 0; j < 8; j++) red[g][j*64+d] = acc[j];
    __syncthreads();
    #pragma unroll
    for (int o = 0; o < 2; o++) {
        int idx = t + 256*o;
        atomicAdd(&g_t[idx], red[0][idx]+red[1][idx]+red[2][idx]+red[3][idx]);
    }
}

// B[i,j] (=|+=) (1/JB)*sum_d M[i,j,d]*t[j,d]; g_c = softmax(B)[7,:]
template <bool FIRST>
__global__ __launch_bounds__(512) void k_route2() {
    __shared__ float ts[512];
    int t = threadIdx.x;           // 512
    ts[t] = g_t[t];
    __syncthreads();
    g_t[t] = 0.f;                  // re-arm for next reduction / next replay
    if (t < 64) {
        int j = t & 7;
        const float4* mp = (const float4*)(g_M + t*64);
        const float* tp = ts + j*64;
        float s = 0.f;
        #pragma unroll
        for (int k = 0; k < 16; k++) {
            float4 v = mp[k];
            s += v.x*tp[4*k] + v.y*tp[4*k+1] + v.z*tp[4*k+2] + v.w*tp[4*k+3];
        }
        s *= (1.f/16384.f);
        if (FIRST) g_B[t] = s;     // B was 0 before iteration 1
        else       g_B[t] += s;
    }
    __syncthreads();
    if (t < 8) {
        float m = g_B[t];
        #pragma unroll
        for (int i = 1; i < 8; i++) m = fmaxf(m, g_B[i*8+t]);
        float sum = 0.f, e7 = 0.f;
        #pragma unroll
        for (int i = 0; i < 8; i++) {
            float e = expf(g_B[i*8+t] - m);
            sum += e; if (i == 7) e7 = e;
        }
        g_c[t] = e7/sum;
    }
}

// out[j,b,e] = scal3(j,b) * uhl[j,b,e]  (pure stream; output position == b)
__global__ void k_out(float* __restrict__ out) {
    __shared__ float scal_s[128];
    int j = blockIdx.y, p0 = blockIdx.x * 128, t = threadIdx.x;
    if (t < 128) scal_s[t] = squash_scal(g_c[j], g_n2[j*16384 + p0 + t]);
    __syncthreads();
    const float4* src = (const float4*)(g_uhl + j*1048576 + p0*64);
    float4* dst = (float4*)(out + j*1048576 + p0*64);
    #pragma unroll
    for (int k = 0; k < 8; k++) {
        int idx = k*256 + t;       // 2048 float4
        float4 v = src[idx];
        float s = scal_s[idx >> 4];
        v.x *= s; v.y *= s; v.z *= s; v.w *= s;
        dst[idx] = v;
    }
}

extern "C" void kernel_launch(void* const* d_in, const int* in_sizes, int n_in,
                              void* d_out, int out_size) {
    const float* x = (const float*)d_in[0];
    const float* w = (const float*)d_in[1];
    float* out = (float*)d_out;
    k_gemm<<<dim3(256, 4), 128>>>(x, w);       // uhl, n2, t1 (c=1/8)
    k_umean<<<dim3(32, 8), 256>>>(x);
    k_uhm<<<16, 256>>>(w);                     // uhm -> M
    k_route2<true><<<1, 512>>>();              // B1, c2
    k_route1<<<512, 256>>>(x);                 // t2
    k_route2<false><<<1, 512>>>();             // B2, c3
    k_out<<<dim3(128, 8), 256>>>(out);
}

// round 14
// speedup vs baseline: 1.4536x; 1.0306x over previous
#include <cuda_runtime.h>

typedef unsigned long long ull;

#define X7    (7*1048576)      // x[7] offset (floats)
#define W7OFF (7*8*4096)       // weights[7] offset (floats)

// Scratch (device globals — no allocations allowed)
__device__ float g_uhl[8*16384*64];  // [j][b][e] 32MB
__device__ float g_n2[8*16384];      // [j][b]
__device__ float g_umpart[32*512];   // per-block partial sums of u over b
__device__ float g_M[4096];          // M[i,j,d] = sum_e uhm[i,j,e]*W7[j,d,e]
__device__ float g_t1[512];          // [j][d] routing reduction 1 (zeroed by k_umean)
__device__ float g_t2[512];          // [j][d] routing reduction 2 (zeroed by k_umean)

__device__ __forceinline__ void fma2(ull &acc, ull a, ull b) {
    asm("fma.rn.f32x2 %0, %1, %2, %0;" : "+l"(acc) : "l"(a), "l"(b));
}
__device__ __forceinline__ ull pack2(float x) {
    unsigned u = __float_as_uint(x);
    ull r; asm("mov.b64 %0, {%1, %1};" : "=l"(r) : "r"(u)); return r;
}
__device__ __forceinline__ float2 unpack2(ull v) {
    unsigned lo, hi;
    asm("mov.b64 {%0, %1}, %2;" : "=r"(lo), "=r"(hi) : "l"(v));
    return make_float2(__uint_as_float(lo), __uint_as_float(hi));
}
__device__ __forceinline__ float squash_scal(float cj, float n2v) {
    float s2 = cj*cj*n2v;
    return cj*s2 / ((1.f+s2)*sqrtf(s2+1e-9f));
}
// x[7] memory row for u-row b:  u[b,7,d] = x[7, b&31, b>>5, d]
__device__ __forceinline__ int xrow(int b) {
    return (b & 31)*512 + (b >> 5);
}
// dot of 64 contiguous floats (float4 pattern shared by all B computations)
__device__ __forceinline__ float dot64(const float* __restrict__ a,
                                       const float* __restrict__ b) {
    const float4* ap = (const float4*)a;
    float s = 0.f;
    #pragma unroll
    for (int k = 0; k < 16; k++) {
        float4 v = ap[k];
        s += v.x*b[4*k] + v.y*b[4*k+1] + v.z*b[4*k+2] + v.w*b[4*k+3];
    }
    return s;
}

// sum over rows of x[i] -> g_umpart[bx][i*64+d]. Also zeroes g_t1/g_t2
// (runs FIRST in the stream; gemm's atomics come after -> no race).
__global__ __launch_bounds__(256) void k_umean(const float* __restrict__ x) {
    __shared__ float4 red[16][16];
    int i = blockIdx.y, bx = blockIdx.x, t = threadIdx.x;
    if (i == 0 && bx == 0) {
        g_t1[t] = 0.f; g_t1[t+256] = 0.f;
        g_t2[t] = 0.f; g_t2[t+256] = 0.f;
    }
    int dq = (t & 15) * 4, g = t >> 4;          // 16 d-quads, 16 row-groups
    const float* xp = x + i*1048576 + (bx*512 + g*32)*64 + dq;
    float4 acc = make_float4(0.f,0.f,0.f,0.f);
    #pragma unroll 8
    for (int m = 0; m < 32; m++) {
        float4 v = *(const float4*)(xp + m*64);
        acc.x += v.x; acc.y += v.y; acc.z += v.z; acc.w += v.w;
    }
    red[g][t & 15] = acc;
    __syncthreads();
    if (t < 16) {
        float4 s = make_float4(0.f,0.f,0.f,0.f);
        #pragma unroll
        for (int gg = 0; gg < 16; gg++) {
            float4 v = red[gg][t];
            s.x += v.x; s.y += v.y; s.z += v.z; s.w += v.w;
        }
        *(float4*)&g_umpart[bx*512 + i*64 + t*4] = s;
    }
}

// uhm[i,j,e] = sum_d W[i,j,d,e]*umean[i,d]  (kept in smem), then
// M[i,j,d]  = sum_e uhm[i,j,e]*W7[j,d,e]   (contiguous W7 reads).
// 16 blocks x 4 ij each.
__global__ __launch_bounds__(256) void k_uhm(const float* __restrict__ w) {
    __shared__ float um[512];
    __shared__ float uhm_s[4][64];
    int t = threadIdx.x;           // 256
    #pragma unroll
    for (int o = 0; o < 2; o++) {
        int idx = t + 256*o;
        float s = 0.f;
        #pragma unroll
        for (int bx = 0; bx < 32; bx++) s += g_umpart[bx*512 + idx];
        um[idx] = s * (1.f/16384.f);
    }
    __syncthreads();
    int q = t >> 6, e = t & 63;    // q: local ij 0..3
    int ij = blockIdx.x*4 + q;
    int i = ij >> 3, j = ij & 7;
    {
        const float* wp = w + ij*4096 + e;
        const float* up = um + i*64;
        float s = 0.f;
        #pragma unroll 8
        for (int d = 0; d < 64; d++) s += wp[d*64] * up[d];
        uhm_s[q][e] = s;
    }
    __syncthreads();
    g_M[ij*64 + e] = dot64(w + W7OFF + j*4096 + e*64, uhm_s[q]);
}

// uhl[j,b,e] = sum_d u[b,7,d]*W7[j,d,e]; n2[j,b] = sum_e uhl^2.
// ALSO fuses routing iteration 1 (c = 1/8 exactly since B=0):
//   g_t1[j,d] += sum_b squash_scal(1/8, n2[b,j]) * u[b,7,d]
// grid (256 p-blocks, 4 j-pairs); 64 rows/block, 2 j per block.
__global__ __launch_bounds__(128, 6) void k_gemm(const float* __restrict__ x,
                                                 const float* __restrict__ w) {
    __shared__ float xs[64*65];      // [d][row], stride 65 (conflict-free column reads)
    __shared__ float ws[64*64];      // [d][col] 16KB
    __shared__ float scal_sm[2][64]; // squash_scal(1/8, n2) per (jj, row)
    int t = threadIdx.x;             // 128
    int p0 = blockIdx.x * 64;        // b-block base
    int j0 = blockIdx.y * 2;

    {   // load + transpose 64 u-rows (gather from permuted x layout)
        int rp_ = t & 31, q = t >> 5;      // q: d-chunk of 16
        int bA = p0 + 2*rp_;
        const float* pa = x + X7 + xrow(bA)*64 + q*16;
        const float* pb = x + X7 + xrow(bA+1)*64 + q*16;
        #pragma unroll
        for (int i = 0; i < 4; i++) {
            float4 a = *(const float4*)(pa + 4*i);
            float4 b = *(const float4*)(pb + 4*i);
            int d0 = q*16 + 4*i;
            xs[(d0+0)*65 + 2*rp_] = a.x; xs[(d0+0)*65 + 2*rp_+1] = b.x;
            xs[(d0+1)*65 + 2*rp_] = a.y; xs[(d0+1)*65 + 2*rp_+1] = b.y;
            xs[(d0+2)*65 + 2*rp_] = a.z; xs[(d0+2)*65 + 2*rp_+1] = b.z;
            xs[(d0+3)*65 + 2*rp_] = a.w; xs[(d0+3)*65 + 2*rp_+1] = b.w;
        }
    }

    int cg = t & 7, rq = t >> 3;
    int r0 = rq * 4;

    #pragma unroll
    for (int jj = 0; jj < 2; jj++) {
        int j = j0 + jj;
        __syncthreads();
        {   // fill W tile (natural layout)
            const float* W7p = w + W7OFF + j*4096;
            #pragma unroll
            for (int k = 0; k < 8; k++) {
                int idx = t + 128*k;
                *(float4*)(ws + idx*4) = *(const float4*)(W7p + idx*4);
            }
        }
        __syncthreads();

        // acc[r][m]: m=0,1 -> cols 4cg..4cg+3 ; m=2,3 -> cols 32+4cg..+3
        ull acc[4][4];
        #pragma unroll
        for (int r = 0; r < 4; r++)
            #pragma unroll
            for (int m = 0; m < 4; m++) acc[r][m] = 0ULL;

        #pragma unroll 8
        for (int d = 0; d < 64; d++) {
            ulonglong2 w0 = *(const ulonglong2*)&ws[d*64 + cg*4];
            ulonglong2 w1 = *(const ulonglong2*)&ws[d*64 + 32 + cg*4];
            ull xr[4];
            #pragma unroll
            for (int r = 0; r < 4; r++) xr[r] = pack2(xs[d*65 + r0 + r]);
            #pragma unroll
            for (int r = 0; r < 4; r++) {
                fma2(acc[r][0], xr[r], w0.x);
                fma2(acc[r][1], xr[r], w0.y);
                fma2(acc[r][2], xr[r], w1.x);
                fma2(acc[r][3], xr[r], w1.y);
            }
        }

        #pragma unroll
        for (int r = 0; r < 4; r++) {
            float2 v0 = unpack2(acc[r][0]), v1 = unpack2(acc[r][1]);
            float2 v2 = unpack2(acc[r][2]), v3 = unpack2(acc[r][3]);
            int row = p0 + r0 + r;
            float* base = g_uhl + j*1048576 + row*64;
            *(float4*)(base + 4*cg)      = make_float4(v0.x, v0.y, v1.x, v1.y);
            *(float4*)(base + 32 + 4*cg) = make_float4(v2.x, v2.y, v3.x, v3.y);

            float s = v0.x*v0.x + v0.y*v0.y + v1.x*v1.x + v1.y*v1.y
                    + v2.x*v2.x + v2.y*v2.y + v3.x*v3.x + v3.y*v3.y;
            #pragma unroll
            for (int off = 1; off < 8; off <<= 1)
                s += __shfl_xor_sync(~0u, s, off);
            if (cg == 0) {
                g_n2[j*16384 + row] = s;
                scal_sm[jj][r0 + r] = squash_scal(0.125f, s);
            }
        }
    }

    // Fused routing iteration 1: t1[jj][d] = sum_r scal_sm[jj][r] * x[r][d]
    __syncthreads();
    {
        int d = t & 63, jj2 = t >> 6;
        float acc = 0.f;
        #pragma unroll 16
        for (int r = 0; r < 64; r++)
            acc += scal_sm[jj2][r] * xs[d*65 + r];
        atomicAdd(&g_t1[(j0 + jj2)*64 + d], acc);
    }
}

// routing reduction 2. Prologue (redundant per block): B1 = M.t1/JB,
// c2 = softmax(B1)[7,:]. Then t2[j,d] += scal(b,j)*u[b,7,d].
// grid 512 blocks x 32 rows.
__global__ __launch_bounds__(256) void k_route1(const float* __restrict__ x) {
    __shared__ float ts[512], Bsm[64], c_s[8];
    __shared__ float scal_s[32*8];
    __shared__ float red[4][512];
    int t = threadIdx.x;
    ts[t] = g_t1[t]; ts[t+256] = g_t1[t+256];
    __syncthreads();
    if (t < 64)
        Bsm[t] = dot64(g_M + t*64, ts + (t & 7)*64) * (1.f/16384.f);
    __syncthreads();
    if (t < 8) {
        float m = Bsm[t];
        #pragma unroll
        for (int i = 1; i < 8; i++) m = fmaxf(m, Bsm[i*8+t]);
        float sum = 0.f, e7 = 0.f;
        #pragma unroll
        for (int i = 0; i < 8; i++) {
            float e = expf(Bsm[i*8+t] - m);
            sum += e; if (i == 7) e7 = e;
        }
        c_s[t] = e7/sum;
    }
    __syncthreads();
    int p0 = blockIdx.x * 32;
    {   // scal table: 256 entries, 1 per thread
        int r = t >> 3, j = t & 7;
        scal_s[t] = squash_scal(c_s[j], g_n2[j*16384 + p0 + r]);
    }
    __syncthreads();
    int d = t & 63, g = t >> 6;          // 4 groups x 8 rows
    const float* xb = x + X7 + d;
    float xv[8];
    #pragma unroll
    for (int m = 0; m < 8; m++)          // 8 independent loads in flight
        xv[m] = xb[xrow(p0 + g*8 + m)*64];
    float acc[8] = {0,0,0,0,0,0,0,0};
    #pragma unroll
    for (int m = 0; m < 8; m++) {
        int r = g*8 + m;
        #pragma unroll
        for (int j = 0; j < 8; j++) acc[j] += scal_s[r*8+j] * xv[m];
    }
    #pragma unroll
    for (int j = 0; j < 8; j++) red[g][j*64+d] = acc[j];
    __syncthreads();
    #pragma unroll
    for (int o = 0; o < 2; o++) {
        int idx = t + 256*o;
        atomicAdd(&g_t2[idx], red[0][idx]+red[1][idx]+red[2][idx]+red[3][idx]);
    }
}

// out[j,b,e] = scal3(j,b) * uhl[j,b,e].
// Prologue (redundant per block): B2[:,j] = M[:,j,:].(t1+t2)[j,:]/JB for own j,
// c3_j = softmax column. grid (64, 8), 256 rows/block.
__global__ __launch_bounds__(256) void k_out(float* __restrict__ out) {
    __shared__ float tj[64], Bcol[8], scal_s[256];
    __shared__ float c3;
    int j = blockIdx.y, p0 = blockIdx.x * 256, t = threadIdx.x;
    if (t < 64) tj[t] = g_t1[j*64 + t] + g_t2[j*64 + t];
    __syncthreads();
    if (t < 8)
        Bcol[t] = dot64(g_M + (t*8 + j)*64, tj) * (1.f/16384.f);
    __syncthreads();
    if (t == 0) {
        float m = Bcol[0];
        #pragma unroll
        for (int i = 1; i < 8; i++) m = fmaxf(m, Bcol[i]);
        float sum = 0.f;
        #pragma unroll
        for (int i = 0; i < 8; i++) sum += expf(Bcol[i] - m);
        c3 = expf(Bcol[7] - m) / sum;
    }
    __syncthreads();
    scal_s[t] = squash_scal(c3, g_n2[j*16384 + p0 + t]);
    __syncthreads();
    const float4* src = (const float4*)(g_uhl + j*1048576 + p0*64);
    float4* dst = (float4*)(out + j*1048576 + p0*64);
    #pragma unroll
    for (int k = 0; k < 16; k++) {
        int idx = k*256 + t;       // 4096 float4
        float4 v = src[idx];
        float s = scal_s[idx >> 4];
        v.x *= s; v.y *= s; v.z *= s; v.w *= s;
        dst[idx] = v;
    }
}

extern "C" void kernel_launch(void* const* d_in, const int* in_sizes, int n_in,
                              void* d_out, int out_size) {
    const float* x = (const float*)d_in[0];
    const float* w = (const float*)d_in[1];
    float* out = (float*)d_out;
    k_umean<<<dim3(32, 8), 256>>>(x);          // umpart; zero t1/t2
    k_gemm<<<dim3(256, 4), 128>>>(x, w);       // uhl, n2, t1 (c=1/8)
    k_uhm<<<16, 256>>>(w);                     // M
    k_route1<<<512, 256>>>(x);                 // B1,c2 (redundant); t2
    k_out<<<dim3(64, 8), 256>>>(out);          // B2,c3 (redundant); stream
}

// round 15
// speedup vs baseline: 1.6121x; 1.1090x over previous
#include <cuda_runtime.h>

typedef unsigned long long ull;

#define X7    (7*1048576)      // x[7] offset (floats)
#define W7OFF (7*8*4096)       // weights[7] offset (floats)

// Scratch (device globals — no allocations allowed)
__device__ float g_uhl[8*16384*64];  // [j][b][e] 32MB
__device__ float g_n2[8*16384];      // [j][b]
__device__ float g_umpart[32*512];   // per-block partial sums of u over b
__device__ float g_M[4096];          // M[i,j,d] = sum_e uhm[i,j,e]*W7[j,d,e]
__device__ float g_B1[64];           // B after iteration 1
__device__ float g_t1[512];          // routing reduction 1 (zeroed by route1 after use)
__device__ float g_t2[512];          // routing reduction 2 (zeroed by k_main; holds t1+t2 for k_out)

__device__ __forceinline__ void fma2(ull &acc, ull a, ull b) {
    asm("fma.rn.f32x2 %0, %1, %2, %0;" : "+l"(acc) : "l"(a), "l"(b));
}
__device__ __forceinline__ ull pack2(float x) {
    unsigned u = __float_as_uint(x);
    ull r; asm("mov.b64 %0, {%1, %1};" : "=l"(r) : "r"(u)); return r;
}
__device__ __forceinline__ float2 unpack2(ull v) {
    unsigned lo, hi;
    asm("mov.b64 {%0, %1}, %2;" : "=r"(lo), "=r"(hi) : "l"(v));
    return make_float2(__uint_as_float(lo), __uint_as_float(hi));
}
__device__ __forceinline__ float squash_scal(float cj, float n2v) {
    float s2 = cj*cj*n2v;
    return cj*s2 / ((1.f+s2)*sqrtf(s2+1e-9f));
}
// x[7] memory row for u-row b:  u[b,7,d] = x[7, b&31, b>>5, d]
__device__ __forceinline__ int xrow(int b) {
    return (b & 31)*512 + (b >> 5);
}
// dot of 64 contiguous floats
__device__ __forceinline__ float dot64(const float* __restrict__ a,
                                       const float* __restrict__ b) {
    const float4* ap = (const float4*)a;
    float s = 0.f;
    #pragma unroll
    for (int k = 0; k < 16; k++) {
        float4 v = ap[k];
        s += v.x*b[4*k] + v.y*b[4*k+1] + v.z*b[4*k+2] + v.w*b[4*k+3];
    }
    return s;
}

// k_main: grid (256, 5) x 128 threads.
//  y<4 : GEMM slices — uhl[j,b,e], n2[j,b], t1 (c=1/8 fused routing iter 1)
//  y==4: umean slice — g_umpart partials over x[i]; bx==0 also zeroes t2
//        (t2 atomics happen 2 kernels later in route1 — no race).
__global__ __launch_bounds__(128, 6) void k_main(const float* __restrict__ x,
                                                 const float* __restrict__ w) {
    int t = threadIdx.x;             // 128

    if (blockIdx.y == 4) {           // ---- umean path ----
        __shared__ float4 red[8][16];
        int bx = blockIdx.x;
        int i = bx >> 5, sub = bx & 31;
        if (bx == 0) {
            g_t2[t] = 0.f; g_t2[t+128] = 0.f; g_t2[t+256] = 0.f; g_t2[t+384] = 0.f;
        }
        int dq = (t & 15) * 4, g = t >> 4;     // 8 groups x 64 rows
        const float* xp = x + i*1048576 + (sub*512 + g*64)*64 + dq;
        float4 acc = make_float4(0.f,0.f,0.f,0.f);
        #pragma unroll 8
        for (int m = 0; m < 64; m++) {
            float4 v = *(const float4*)(xp + m*64);
            acc.x += v.x; acc.y += v.y; acc.z += v.z; acc.w += v.w;
        }
        red[g][t & 15] = acc;
        __syncthreads();
        if (t < 16) {
            float4 s = make_float4(0.f,0.f,0.f,0.f);
            #pragma unroll
            for (int gg = 0; gg < 8; gg++) {
                float4 v = red[gg][t];
                s.x += v.x; s.y += v.y; s.z += v.z; s.w += v.w;
            }
            *(float4*)&g_umpart[sub*512 + i*64 + t*4] = s;
        }
        return;
    }

    // ---- GEMM path ----
    __shared__ float xs[64*65];      // [d][row], stride 65
    __shared__ float ws[64*64];      // [d][col]
    __shared__ float scal_sm[2][64];
    int p0 = blockIdx.x * 64;        // b-block base
    int j0 = blockIdx.y * 2;

    {   // load + transpose 64 u-rows (gather from permuted x layout)
        int rp_ = t & 31, q = t >> 5;
        int bA = p0 + 2*rp_;
        const float* pa = x + X7 + xrow(bA)*64 + q*16;
        const float* pb = x + X7 + xrow(bA+1)*64 + q*16;
        #pragma unroll
        for (int i = 0; i < 4; i++) {
            float4 a = *(const float4*)(pa + 4*i);
            float4 b = *(const float4*)(pb + 4*i);
            int d0 = q*16 + 4*i;
            xs[(d0+0)*65 + 2*rp_] = a.x; xs[(d0+0)*65 + 2*rp_+1] = b.x;
            xs[(d0+1)*65 + 2*rp_] = a.y; xs[(d0+1)*65 + 2*rp_+1] = b.y;
            xs[(d0+2)*65 + 2*rp_] = a.z; xs[(d0+2)*65 + 2*rp_+1] = b.z;
            xs[(d0+3)*65 + 2*rp_] = a.w; xs[(d0+3)*65 + 2*rp_+1] = b.w;
        }
    }

    int cg = t & 7, rq = t >> 3;
    int r0 = rq * 4;

    #pragma unroll
    for (int jj = 0; jj < 2; jj++) {
        int j = j0 + jj;
        __syncthreads();
        {   // fill W tile (natural layout)
            const float* W7p = w + W7OFF + j*4096;
            #pragma unroll
            for (int k = 0; k < 8; k++) {
                int idx = t + 128*k;
                *(float4*)(ws + idx*4) = *(const float4*)(W7p + idx*4);
            }
        }
        __syncthreads();

        ull acc[4][4];
        #pragma unroll
        for (int r = 0; r < 4; r++)
            #pragma unroll
            for (int m = 0; m < 4; m++) acc[r][m] = 0ULL;

        #pragma unroll 8
        for (int d = 0; d < 64; d++) {
            ulonglong2 w0 = *(const ulonglong2*)&ws[d*64 + cg*4];
            ulonglong2 w1 = *(const ulonglong2*)&ws[d*64 + 32 + cg*4];
            ull xr[4];
            #pragma unroll
            for (int r = 0; r < 4; r++) xr[r] = pack2(xs[d*65 + r0 + r]);
            #pragma unroll
            for (int r = 0; r < 4; r++) {
                fma2(acc[r][0], xr[r], w0.x);
                fma2(acc[r][1], xr[r], w0.y);
                fma2(acc[r][2], xr[r], w1.x);
                fma2(acc[r][3], xr[r], w1.y);
            }
        }

        #pragma unroll
        for (int r = 0; r < 4; r++) {
            float2 v0 = unpack2(acc[r][0]), v1 = unpack2(acc[r][1]);
            float2 v2 = unpack2(acc[r][2]), v3 = unpack2(acc[r][3]);
            int row = p0 + r0 + r;
            float* base = g_uhl + j*1048576 + row*64;
            *(float4*)(base + 4*cg)      = make_float4(v0.x, v0.y, v1.x, v1.y);
            *(float4*)(base + 32 + 4*cg) = make_float4(v2.x, v2.y, v3.x, v3.y);

            float s = v0.x*v0.x + v0.y*v0.y + v1.x*v1.x + v1.y*v1.y
                    + v2.x*v2.x + v2.y*v2.y + v3.x*v3.x + v3.y*v3.y;
            #pragma unroll
            for (int off = 1; off < 8; off <<= 1)
                s += __shfl_xor_sync(~0u, s, off);
            if (cg == 0) {
                g_n2[j*16384 + row] = s;
                scal_sm[jj][r0 + r] = squash_scal(0.125f, s);
            }
        }
    }

    // Fused routing iteration 1: t1[jj][d] = sum_r scal_sm[jj][r] * x[r][d]
    __syncthreads();
    {
        int d = t & 63, jj2 = t >> 6;
        float acc = 0.f;
        #pragma unroll 16
        for (int r = 0; r < 64; r++)
            acc += scal_sm[jj2][r] * xs[d*65 + r];
        atomicAdd(&g_t1[(j0 + jj2)*64 + d], acc);
    }
}

// uhm -> M -> B1.  16 blocks x 4 ij each.  Runs after k_main: t1 complete.
__global__ __launch_bounds__(256) void k_uhm(const float* __restrict__ w) {
    __shared__ float um[512], t1s[512];
    __shared__ float uhm_s[4][64], Ms[4][64];
    int t = threadIdx.x;           // 256
    #pragma unroll
    for (int o = 0; o < 2; o++) {
        int idx = t + 256*o;
        float s = 0.f;
        #pragma unroll
        for (int bx = 0; bx < 32; bx++) s += g_umpart[bx*512 + idx];
        um[idx] = s * (1.f/16384.f);
        t1s[idx] = g_t1[idx];
    }
    __syncthreads();
    int q = t >> 6, e = t & 63;    // q: local ij 0..3
    int ij = blockIdx.x*4 + q;
    int i = ij >> 3, j = ij & 7;
    {
        const float* wp = w + ij*4096 + e;
        const float* up = um + i*64;
        float s = 0.f;
        #pragma unroll 8
        for (int d = 0; d < 64; d++) s += wp[d*64] * up[d];
        uhm_s[q][e] = s;
    }
    __syncthreads();
    {
        float mval = dot64(w + W7OFF + j*4096 + e*64, uhm_s[q]);
        g_M[ij*64 + e] = mval;
        Ms[q][e] = mval;
    }
    __syncthreads();
    if (t < 4) {
        int ij2 = blockIdx.x*4 + t, j2 = ij2 & 7;
        g_B1[ij2] = dot64(Ms[t], t1s + j2*64) * (1.f/16384.f);
    }
}

// routing reduction 2: c2 = softmax(B1)[7,:]; t2[j,d] += scal(b,j)*u[b,7,d].
// Block 0 also folds t1 into t2 (atomicAdd, commutes) and zeroes t1.
// grid 512 blocks x 32 rows.
__global__ __launch_bounds__(256) void k_route1(const float* __restrict__ x) {
    __shared__ float Bsm[64], c_s[8];
    __shared__ float scal_s[32*8];
    __shared__ float red[4][512];
    int t = threadIdx.x;
    if (t < 64) Bsm[t] = g_B1[t];
    if (blockIdx.x == 0) {
        float v1 = g_t1[t], v2 = g_t1[t+256];
        atomicAdd(&g_t2[t], v1);
        atomicAdd(&g_t2[t+256], v2);
        g_t1[t] = 0.f; g_t1[t+256] = 0.f;   // re-arm for next replay
    }
    __syncthreads();
    if (t < 8) {
        float m = Bsm[t];
        #pragma unroll
        for (int i = 1; i < 8; i++) m = fmaxf(m, Bsm[i*8+t]);
        float sum = 0.f, e7 = 0.f;
        #pragma unroll
        for (int i = 0; i < 8; i++) {
            float e = expf(Bsm[i*8+t] - m);
            sum += e; if (i == 7) e7 = e;
        }
        c_s[t] = e7/sum;
    }
    __syncthreads();
    int p0 = blockIdx.x * 32;
    {   // scal table: 256 entries, 1 per thread
        int r = t >> 3, j = t & 7;
        scal_s[t] = squash_scal(c_s[j], g_n2[j*16384 + p0 + r]);
    }
    __syncthreads();
    int d = t & 63, g = t >> 6;          // 4 groups x 8 rows
    const float* xb = x + X7 + d;
    float xv[8];
    #pragma unroll
    for (int m = 0; m < 8; m++)
        xv[m] = xb[xrow(p0 + g*8 + m)*64];
    float acc[8] = {0,0,0,0,0,0,0,0};
    #pragma unroll
    for (int m = 0; m < 8; m++) {
        int r = g*8 + m;
        #pragma unroll
        for (int j = 0; j < 8; j++) acc[j] += scal_s[r*8+j] * xv[m];
    }
    #pragma unroll
    for (int j = 0; j < 8; j++) red[g][j*64+d] = acc[j];
    __syncthreads();
    #pragma unroll
    for (int o = 0; o < 2; o++) {
        int idx = t + 256*o;
        atomicAdd(&g_t2[idx], red[0][idx]+red[1][idx]+red[2][idx]+red[3][idx]);
    }
}

// out[j,b,e] = scal3(j,b) * uhl[j,b,e].
// Prologue (redundant per block): B2[:,j] = M[:,j,:].(t1+t2)[j,:]/JB (t2 holds sum),
// c3_j = softmax column. grid (64, 8), 256 rows/block.
__global__ __launch_bounds__(256) void k_out(float* __restrict__ out) {
    __shared__ float tj[64], Bcol[8], scal_s[256];
    __shared__ float c3;
    int j = blockIdx.y, p0 = blockIdx.x * 256, t = threadIdx.x;
    if (t < 64) tj[t] = g_t2[j*64 + t];
    __syncthreads();
    if (t < 8)
        Bcol[t] = dot64(g_M + (t*8 + j)*64, tj) * (1.f/16384.f);
    __syncthreads();
    if (t == 0) {
        float m = Bcol[0];
        #pragma unroll
        for (int i = 1; i < 8; i++) m = fmaxf(m, Bcol[i]);
        float sum = 0.f;
        #pragma unroll
        for (int i = 0; i < 8; i++) sum += expf(Bcol[i] - m);
        c3 = expf(Bcol[7] - m) / sum;
    }
    __syncthreads();
    scal_s[t] = squash_scal(c3, g_n2[j*16384 + p0 + t]);
    __syncthreads();
    const float4* src = (const float4*)(g_uhl + j*1048576 + p0*64);
    float4* dst = (float4*)(out + j*1048576 + p0*64);
    #pragma unroll
    for (int k = 0; k < 16; k++) {
        int idx = k*256 + t;       // 4096 float4
        float4 v = src[idx];
        float s = scal_s[idx >> 4];
        v.x *= s; v.y *= s; v.z *= s; v.w *= s;
        dst[idx] = v;
    }
}

extern "C" void kernel_launch(void* const* d_in, const int* in_sizes, int n_in,
                              void* d_out, int out_size) {
    const float* x = (const float*)d_in[0];
    const float* w = (const float*)d_in[1];
    float* out = (float*)d_out;
    k_main<<<dim3(256, 5), 128>>>(x, w);       // gemm(uhl,n2,t1) + umean; zero t2
    k_uhm<<<16, 256>>>(w);                     // um -> uhm -> M -> B1
    k_route1<<<512, 256>>>(x);                 // c2; t2 += route2; t2 += t1; t1 = 0
    k_out<<<dim3(64, 8), 256>>>(out);          // B2,c3 (per block); stream out
}

// round 16
// speedup vs baseline: 1.6452x; 1.0205x over previous
#include <cuda_runtime.h>

typedef unsigned long long ull;

#define X7    (7*1048576)      // x[7] offset (floats)
#define W7OFF (7*8*4096)       // weights[7] offset (floats)

// Scratch (device globals — no allocations allowed)
__device__ float g_uhl[8*16384*64];  // [j][b][e] 32MB
__device__ float g_n2[8*16384];      // [j][b]
__device__ float g_umpart[32*512];   // per-block partial sums of u over b
__device__ float g_M[4096];          // M[i,j,d] = sum_e uhm[i,j,e]*W7[j,d,e]
__device__ float g_B1[64];           // B after iteration 1
__device__ float g_t1[512];          // routing reduction 1 (zeroed by route1 after use)
__device__ float g_t2[512];          // t1+t2 accumulator for k_out (zeroed by k_main)

__device__ __forceinline__ void fma2(ull &acc, ull a, ull b) {
    asm("fma.rn.f32x2 %0, %1, %2, %0;" : "+l"(acc) : "l"(a), "l"(b));
}
__device__ __forceinline__ ull pack2(float x) {
    unsigned u = __float_as_uint(x);
    ull r; asm("mov.b64 %0, {%1, %1};" : "=l"(r) : "r"(u)); return r;
}
__device__ __forceinline__ float2 unpack2(ull v) {
    unsigned lo, hi;
    asm("mov.b64 {%0, %1}, %2;" : "=r"(lo), "=r"(hi) : "l"(v));
    return make_float2(__uint_as_float(lo), __uint_as_float(hi));
}
__device__ __forceinline__ float squash_scal(float cj, float n2v) {
    float s2 = cj*cj*n2v;
    return cj*s2 / ((1.f+s2)*sqrtf(s2+1e-9f));
}
// x[7] memory row for u-row b:  u[b,7,d] = x[7, b&31, b>>5, d]
__device__ __forceinline__ int xrow(int b) {
    return (b & 31)*512 + (b >> 5);
}
// dot of 64 contiguous floats
__device__ __forceinline__ float dot64(const float* __restrict__ a,
                                       const float* __restrict__ b) {
    const float4* ap = (const float4*)a;
    float s = 0.f;
    #pragma unroll
    for (int k = 0; k < 16; k++) {
        float4 v = ap[k];
        s += v.x*b[4*k] + v.y*b[4*k+1] + v.z*b[4*k+2] + v.w*b[4*k+3];
    }
    return s;
}

// k_main: grid (256, 5) x 128 threads.
//  y<4 : GEMM slices — uhl[j,b,e], n2[j,b], t1 (c=1/8 fused routing iter 1)
//  y==4: umean slice — g_umpart partials over x[i]; bx==0 also zeroes t2.
__global__ __launch_bounds__(128, 6) void k_main(const float* __restrict__ x,
                                                 const float* __restrict__ w) {
    int t = threadIdx.x;             // 128

    if (blockIdx.y == 4) {           // ---- umean path ----
        __shared__ float4 red[8][16];
        int bx = blockIdx.x;
        int i = bx >> 5, sub = bx & 31;
        if (bx == 0) {
            g_t2[t] = 0.f; g_t2[t+128] = 0.f; g_t2[t+256] = 0.f; g_t2[t+384] = 0.f;
        }
        int dq = (t & 15) * 4, g = t >> 4;     // 8 groups x 64 rows
        const float* xp = x + i*1048576 + (sub*512 + g*64)*64 + dq;
        float4 acc = make_float4(0.f,0.f,0.f,0.f);
        #pragma unroll 8
        for (int m = 0; m < 64; m++) {
            float4 v = *(const float4*)(xp + m*64);
            acc.x += v.x; acc.y += v.y; acc.z += v.z; acc.w += v.w;
        }
        red[g][t & 15] = acc;
        __syncthreads();
        if (t < 16) {
            float4 s = make_float4(0.f,0.f,0.f,0.f);
            #pragma unroll
            for (int gg = 0; gg < 8; gg++) {
                float4 v = red[gg][t];
                s.x += v.x; s.y += v.y; s.z += v.z; s.w += v.w;
            }
            *(float4*)&g_umpart[sub*512 + i*64 + t*4] = s;
        }
        return;
    }

    // ---- GEMM path ----
    __shared__ float xs[64*65];      // [d][row], stride 65
    __shared__ float ws[64*64];      // [d][col]
    __shared__ float scal_sm[2][64];
    int p0 = blockIdx.x * 64;        // b-block base
    int j0 = blockIdx.y * 2;

    {   // load + transpose 64 u-rows (gather from permuted x layout)
        int rp_ = t & 31, q = t >> 5;
        int bA = p0 + 2*rp_;
        const float* pa = x + X7 + xrow(bA)*64 + q*16;
        const float* pb = x + X7 + xrow(bA+1)*64 + q*16;
        #pragma unroll
        for (int i = 0; i < 4; i++) {
            float4 a = *(const float4*)(pa + 4*i);
            float4 b = *(const float4*)(pb + 4*i);
            int d0 = q*16 + 4*i;
            xs[(d0+0)*65 + 2*rp_] = a.x; xs[(d0+0)*65 + 2*rp_+1] = b.x;
            xs[(d0+1)*65 + 2*rp_] = a.y; xs[(d0+1)*65 + 2*rp_+1] = b.y;
            xs[(d0+2)*65 + 2*rp_] = a.z; xs[(d0+2)*65 + 2*rp_+1] = b.z;
            xs[(d0+3)*65 + 2*rp_] = a.w; xs[(d0+3)*65 + 2*rp_+1] = b.w;
        }
    }

    int cg = t & 7, rq = t >> 3;
    int r0 = rq * 4;

    #pragma unroll
    for (int jj = 0; jj < 2; jj++) {
        int j = j0 + jj;
        __syncthreads();
        {   // fill W tile (natural layout)
            const float* W7p = w + W7OFF + j*4096;
            #pragma unroll
            for (int k = 0; k < 8; k++) {
                int idx = t + 128*k;
                *(float4*)(ws + idx*4) = *(const float4*)(W7p + idx*4);
            }
        }
        __syncthreads();

        ull acc[4][4];
        #pragma unroll
        for (int r = 0; r < 4; r++)
            #pragma unroll
            for (int m = 0; m < 4; m++) acc[r][m] = 0ULL;

        #pragma unroll 8
        for (int d = 0; d < 64; d++) {
            ulonglong2 w0 = *(const ulonglong2*)&ws[d*64 + cg*4];
            ulonglong2 w1 = *(const ulonglong2*)&ws[d*64 + 32 + cg*4];
            ull xr[4];
            #pragma unroll
            for (int r = 0; r < 4; r++) xr[r] = pack2(xs[d*65 + r0 + r]);
            #pragma unroll
            for (int r = 0; r < 4; r++) {
                fma2(acc[r][0], xr[r], w0.x);
                fma2(acc[r][1], xr[r], w0.y);
                fma2(acc[r][2], xr[r], w1.x);
                fma2(acc[r][3], xr[r], w1.y);
            }
        }

        #pragma unroll
        for (int r = 0; r < 4; r++) {
            float2 v0 = unpack2(acc[r][0]), v1 = unpack2(acc[r][1]);
            float2 v2 = unpack2(acc[r][2]), v3 = unpack2(acc[r][3]);
            int row = p0 + r0 + r;
            float* base = g_uhl + j*1048576 + row*64;
            *(float4*)(base + 4*cg)      = make_float4(v0.x, v0.y, v1.x, v1.y);
            *(float4*)(base + 32 + 4*cg) = make_float4(v2.x, v2.y, v3.x, v3.y);

            float s = v0.x*v0.x + v0.y*v0.y + v1.x*v1.x + v1.y*v1.y
                    + v2.x*v2.x + v2.y*v2.y + v3.x*v3.x + v3.y*v3.y;
            #pragma unroll
            for (int off = 1; off < 8; off <<= 1)
                s += __shfl_xor_sync(~0u, s, off);
            if (cg == 0) {
                g_n2[j*16384 + row] = s;
                scal_sm[jj][r0 + r] = squash_scal(0.125f, s);
            }
        }
    }

    // Fused routing iteration 1: t1[jj][d] = sum_r scal_sm[jj][r] * x[r][d]
    __syncthreads();
    {
        int d = t & 63, jj2 = t >> 6;
        float acc = 0.f;
        #pragma unroll 16
        for (int r = 0; r < 64; r++)
            acc += scal_sm[jj2][r] * xs[d*65 + r];
        atomicAdd(&g_t1[(j0 + jj2)*64 + d], acc);
    }
}

// uhm -> M -> B1.  16 blocks x 4 ij each.  Runs after k_main: t1 complete.
__global__ __launch_bounds__(256) void k_uhm(const float* __restrict__ w) {
    __shared__ float um[512], t1s[512];
    __shared__ float uhm_s[4][64], Ms[4][64];
    int t = threadIdx.x;           // 256
    #pragma unroll
    for (int o = 0; o < 2; o++) {
        int idx = t + 256*o;
        float s = 0.f;
        #pragma unroll
        for (int bx = 0; bx < 32; bx++) s += g_umpart[bx*512 + idx];
        um[idx] = s * (1.f/16384.f);
        t1s[idx] = g_t1[idx];
    }
    __syncthreads();
    int q = t >> 6, e = t & 63;    // q: local ij 0..3
    int ij = blockIdx.x*4 + q;
    int i = ij >> 3, j = ij & 7;
    {
        const float* wp = w + ij*4096 + e;
        const float* up = um + i*64;
        float s = 0.f;
        #pragma unroll 8
        for (int d = 0; d < 64; d++) s += wp[d*64] * up[d];
        uhm_s[q][e] = s;
    }
    __syncthreads();
    {
        float mval = dot64(w + W7OFF + j*4096 + e*64, uhm_s[q]);
        g_M[ij*64 + e] = mval;
        Ms[q][e] = mval;
    }
    __syncthreads();
    if (t < 4) {
        int ij2 = blockIdx.x*4 + t, j2 = ij2 & 7;
        g_B1[ij2] = dot64(Ms[t], t1s + j2*64) * (1.f/16384.f);
    }
}

// routing reduction 2 (PDL consumer of k_uhm).
// Pre-sync: x rows (input) + n2 (k_main output; k_uhm normal launch => k_main done).
// Post-sync: B1 -> c2 -> scal -> FMA -> atomics; block0 folds t1 into t2, zeroes t1.
__global__ __launch_bounds__(256) void k_route1(const float* __restrict__ x) {
    __shared__ float n2s[256], Bsm[64], c_s[8];
    __shared__ float scal_s[256];
    __shared__ float red[4][512];
    int t = threadIdx.x;
    int p0 = blockIdx.x * 32;
    int d = t & 63, g = t >> 6;          // 4 groups x 8 rows

    // ---- pre-sync (independent of k_uhm) ----
    const float* xb = x + X7 + d;
    float xv[8];
    #pragma unroll
    for (int m = 0; m < 8; m++)
        xv[m] = xb[xrow(p0 + g*8 + m)*64];
    {   int r = t >> 3, j = t & 7;
        n2s[t] = g_n2[j*16384 + p0 + r]; }

    cudaGridDependencySynchronize();

    // ---- post-sync ----
    if (t < 64) Bsm[t] = g_B1[t];
    if (blockIdx.x == 0) {
        atomicAdd(&g_t2[t],     g_t1[t]);
        atomicAdd(&g_t2[t+256], g_t1[t+256]);
        g_t1[t] = 0.f; g_t1[t+256] = 0.f;   // re-arm for next replay
    }
    __syncthreads();
    if (t < 8) {
        float m = Bsm[t];
        #pragma unroll
        for (int i = 1; i < 8; i++) m = fmaxf(m, Bsm[i*8+t]);
        float sum = 0.f, e7 = 0.f;
        #pragma unroll
        for (int i = 0; i < 8; i++) {
            float e = expf(Bsm[i*8+t] - m);
            sum += e; if (i == 7) e7 = e;
        }
        c_s[t] = e7/sum;
    }
    __syncthreads();
    scal_s[t] = squash_scal(c_s[t & 7], n2s[t]);
    __syncthreads();
    float acc[8] = {0,0,0,0,0,0,0,0};
    #pragma unroll
    for (int m = 0; m < 8; m++) {
        int r = g*8 + m;
        #pragma unroll
        for (int j = 0; j < 8; j++) acc[j] += scal_s[r*8+j] * xv[m];
    }
    #pragma unroll
    for (int j = 0; j < 8; j++) red[g][j*64+d] = acc[j];
    __syncthreads();
    #pragma unroll
    for (int o = 0; o < 2; o++) {
        int idx = t + 256*o;
        atomicAdd(&g_t2[idx], red[0][idx]+red[1][idx]+red[2][idx]+red[3][idx]);
    }
}

// out[j,b,e] = scal3(j,b)*uhl[j,b,e]  (PDL consumer of route1).
// Pre-sync: batch uhl+n2 loads into regs (k_main outputs; safe — k_uhm's normal
// launch anchors k_main completion before any PDL descendant starts).
// Post-sync: t2 -> B2 col -> c3 -> scale -> store. grid (128, 8), 128 rows/block.
__global__ __launch_bounds__(256) void k_out(float* __restrict__ out) {
    __shared__ float tj[64], Bcol[8], scal_s[128];
    __shared__ float c3;
    int j = blockIdx.y, p0 = blockIdx.x * 128, t = threadIdx.x;

    // ---- pre-sync ----
    const float4* src = (const float4*)(g_uhl + j*1048576 + p0*64);
    float4 v[8];
    #pragma unroll
    for (int k = 0; k < 8; k++) v[k] = src[k*256 + t];
    float n2v = (t < 128) ? g_n2[j*16384 + p0 + t] : 0.f;

    cudaGridDependencySynchronize();

    // ---- post-sync ----
    if (t < 64) tj[t] = g_t2[j*64 + t];
    __syncthreads();
    if (t < 8)
        Bcol[t] = dot64(g_M + (t*8 + j)*64, tj) * (1.f/16384.f);
    __syncthreads();
    if (t == 0) {
        float m = Bcol[0];
        #pragma unroll
        for (int i = 1; i < 8; i++) m = fmaxf(m, Bcol[i]);
        float sum = 0.f;
        #pragma unroll
        for (int i = 0; i < 8; i++) sum += expf(Bcol[i] - m);
        c3 = expf(Bcol[7] - m) / sum;
    }
    __syncthreads();
    if (t < 128) scal_s[t] = squash_scal(c3, n2v);
    __syncthreads();
    float4* dst = (float4*)(out + j*1048576 + p0*64);
    #pragma unroll
    for (int k = 0; k < 8; k++) {
        int idx = k*256 + t;       // 2048 float4
        float s = scal_s[idx >> 4];
        float4 r = v[k];
        r.x *= s; r.y *= s; r.z *= s; r.w *= s;
        dst[idx] = r;
    }
}

extern "C" void kernel_launch(void* const* d_in, const int* in_sizes, int n_in,
                              void* d_out, int out_size) {
    const float* x = (const float*)d_in[0];
    const float* w = (const float*)d_in[1];
    float* out = (float*)d_out;

    k_main<<<dim3(256, 5), 128>>>(x, w);       // gemm(uhl,n2,t1) + umean; zero t2
    k_uhm<<<16, 256>>>(w);                     // um -> uhm -> M -> B1 (normal launch)

    cudaLaunchAttribute attr[1];
    attr[0].id = cudaLaunchAttributeProgrammaticStreamSerialization;
    attr[0].val.programmaticStreamSerializationAllowed = 1;

    cudaLaunchConfig_t cfg = {};
    cfg.attrs = attr;
    cfg.numAttrs = 1;
    cfg.stream = 0;

    cfg.gridDim = dim3(512);
    cfg.blockDim = dim3(256);
    cudaLaunchKernelEx(&cfg, k_route1, x);     // PDL: pre-loads x,n2 under k_uhm

    cfg.gridDim = dim3(128, 8);
    cfg.blockDim = dim3(256);
    cudaLaunchKernelEx(&cfg, k_out, out);      // PDL: pre-loads uhl,n2 under route1
}